// round 14
// baseline (speedup 1.0000x reference)
#include <cuda_runtime.h>

// Output layout: x_hat (64*1*256*256) | ze (64*64*64*64) | zq (64*64*64*64)
#define OFF_ZE 4194304
#define OFF_ZQ 20971520

// Scratch (__device__ globals)
__device__ float g_h1[33554432];   // (64,32,128,128)
__device__ float g_h2[16777216];   // (64,64,64,64)
__device__ float g_dec[16777216];  // (64,64,64,64)
__device__ float g_d1[8388608];    // (64,32,64,64)
__device__ float g_d2[67108864];   // (64,64,128,128)

// ---- packed fp32x2 helpers (sm_103a FFMA2 path; each lane exact IEEE fmaf)
typedef unsigned long long u64;
__device__ __forceinline__ u64 pack2(float f) {
    unsigned u = __float_as_uint(f);
    u64 r;
    asm("mov.b64 %0, {%1, %1};" : "=l"(r) : "r"(u));
    return r;
}
__device__ __forceinline__ void fma2(u64& acc, u64 a, u64 b) {
    asm("fma.rn.f32x2 %0, %1, %2, %0;" : "+l"(acc) : "l"(a), "l"(b));
}
__device__ __forceinline__ float2 unpack2(u64 v) {
    unsigned lo, hi;
    asm("mov.b64 {%0, %1}, %2;" : "=r"(lo), "=r"(hi) : "l"(v));
    return make_float2(__uint_as_float(lo), __uint_as_float(hi));
}

// ===========================================================================
// ENCODER — bit-exact emulation of XLA-CPU/Eigen conv (FROZEN chains)
// ===========================================================================

// e1: conv 1->32, k4 s2 p1. x(64,1,256,256) -> g_h1(64,32,128,128)
__global__ __launch_bounds__(256) void k_e1(const float* __restrict__ x,
                                            const float* __restrict__ w,
                                            const float* __restrict__ b) {
    __shared__ float sw[16][32];   // [tap][o]
    __shared__ float sb[32];
    int t = threadIdx.x;
    {
        int o = t & 31, tap = t >> 5;
        sw[tap][o] = w[o * 16 + tap];
        int e = t + 256; o = e & 31; tap = e >> 5;
        sw[tap][o] = w[o * 16 + tap];
    }
    if (t < 32) sb[t] = b[t];
    __syncthreads();
    int gid = blockIdx.x * 256 + t;
    int ox = gid & 127, oy = (gid >> 7) & 127, n = gid >> 14;
    float acc[32];
#pragma unroll
    for (int o = 0; o < 32; o++) acc[o] = 0.f;
    const float* xin = x + n * 65536;
#pragma unroll
    for (int ky = 0; ky < 4; ky++) {
        int iy = 2 * oy - 1 + ky;
        if (iy < 0 || iy >= 256) continue;
#pragma unroll
        for (int kx = 0; kx < 4; kx++) {
            int ix = 2 * ox - 1 + kx;
            if (ix < 0 || ix >= 256) continue;
            float v = xin[iy * 256 + ix];
#pragma unroll
            for (int o = 0; o < 32; o++) acc[o] = fmaf(v, sw[ky * 4 + kx][o], acc[o]);
        }
    }
    float* op = g_h1 + n * 524288 + oy * 128 + ox;
#pragma unroll
    for (int o = 0; o < 32; o++) op[o * 16384] = fmaxf(__fadd_rn(acc[o], sb[o]), 0.f);
}

// e2: conv 32->64, k4 s2 p1. g_h1 -> g_h2(64,64,64,64)  (R13 form)
#define E2_PITCH 35
#define E2_IN_FLOATS (32 * 34 * E2_PITCH)
#define E2_W_FLOATS  (4 * 32 * 64)
#define E2_SMEM_B   ((E2_IN_FLOATS + E2_W_FLOATS) * 4)
__global__ __launch_bounds__(256, 1) void k_e2(const float* __restrict__ w,
                                               const float* __restrict__ b) {
    extern __shared__ float sm[];
    float* sIn = sm;                 // [ci][34][35]
    float* sw  = sm + E2_IN_FLOATS;  // [kx][ci][o]
    int tid = threadIdx.x;
    int og8 = tid >> 5;
    int sp = tid & 31;
    int r = sp >> 1, h = sp & 1;
    int t_y = blockIdx.x >> 2, t_x = blockIdx.x & 3;
    int n = blockIdx.y;
    int iy0 = 32 * t_y - 1, ix0 = 32 * t_x - 1;
    for (int idx = tid; idx < 32 * 34 * 34; idx += 256) {
        int ci = idx / 1156, rr = idx - ci * 1156;
        int iy = rr / 34, ix = rr - iy * 34;
        int gy = iy0 + iy, gx = ix0 + ix;
        float v = 0.f;
        if (gy >= 0 && gy < 128 && gx >= 0 && gx < 128)
            v = g_h1[((n * 32 + ci) * 128 + gy) * 128 + gx];
        sIn[ci * (34 * E2_PITCH) + iy * E2_PITCH + ix] = v;
    }
    u64 acc2[32];
#pragma unroll
    for (int i = 0; i < 32; i++) acc2[i] = 0ull;
#pragma unroll
    for (int ky = 0; ky < 4; ky++) {
        __syncthreads();
        for (int idx = tid; idx < E2_W_FLOATS; idx += 256) {
            int kx = idx >> 11, ci = (idx >> 6) & 31, o = idx & 63;
            sw[idx] = w[(o * 32 + ci) * 16 + ky * 4 + kx];
        }
        __syncthreads();
#pragma unroll
        for (int kx = 0; kx < 4; kx++) {
            for (int ci = 0; ci < 32; ci++) {
                const float* vb = &sIn[ci * (34 * E2_PITCH) + (2 * r + ky) * E2_PITCH + 16 * h + kx];
                u64 v2[8];
#pragma unroll
                for (int j = 0; j < 8; j++) v2[j] = pack2(vb[2 * j]);
                const ulonglong2* wp = (const ulonglong2*)&sw[(kx * 32 + ci) * 64 + og8 * 8];
                ulonglong2 wA = wp[0], wB = wp[1];
                u64 w2[4] = {wA.x, wA.y, wB.x, wB.y};
#pragma unroll
                for (int j = 0; j < 8; j++)
#pragma unroll
                    for (int o2 = 0; o2 < 4; o2++)
                        fma2(acc2[j * 4 + o2], v2[j], w2[o2]);
            }
        }
    }
    int oy = 16 * t_y + r, ox0 = 16 * t_x + 8 * h;
#pragma unroll
    for (int o2 = 0; o2 < 4; o2++) {
        int o = og8 * 8 + 2 * o2;
        float b0 = b[o], b1 = b[o + 1];
        float* op0 = g_h2 + ((n * 64 + o) * 64 + oy) * 64 + ox0;
        float* op1 = op0 + 4096;
#pragma unroll
        for (int j = 0; j < 8; j++) {
            float2 t2 = unpack2(acc2[j * 4 + o2]);
            op0[j] = fmaxf(__fadd_rn(t2.x, b0), 0.f);
            op1[j] = fmaxf(__fadd_rn(t2.y, b1), 0.f);
        }
    }
}

// e3: conv 64->64, k3 s1 p1. g_h2 -> ze (d_out)  (R13 form)
#define E3_PITCH 21
#define E3_IN_FLOATS (64 * 18 * E3_PITCH)
#define E3_W_FLOATS  (3 * 64 * 64)
#define E3_SMEM_B   ((E3_IN_FLOATS + E3_W_FLOATS) * 4)
__global__ __launch_bounds__(256, 1) void k_e3(const float* __restrict__ w,
                                               const float* __restrict__ b,
                                               float* __restrict__ ze) {
    extern __shared__ float sm[];
    float* sIn = sm;                 // [ci][18][21]
    float* sw  = sm + E3_IN_FLOATS;  // [kx][ci][o]
    int tid = threadIdx.x;
    int og8 = tid >> 5;
    int sp = tid & 31;
    int r = sp >> 1, h = sp & 1;
    int t_y = blockIdx.x >> 2, t_x = blockIdx.x & 3;
    int n = blockIdx.y;
    int iy0 = 16 * t_y - 1, ix0 = 16 * t_x - 1;
    for (int idx = tid; idx < 64 * 18 * 18; idx += 256) {
        int ci = idx / 324, rr = idx - ci * 324;
        int iy = rr / 18, ix = rr - iy * 18;
        int gy = iy0 + iy, gx = ix0 + ix;
        float v = 0.f;
        if (gy >= 0 && gy < 64 && gx >= 0 && gx < 64)
            v = g_h2[((n * 64 + ci) * 64 + gy) * 64 + gx];
        sIn[ci * (18 * E3_PITCH) + iy * E3_PITCH + ix] = v;
    }
    u64 acc2[32];
#pragma unroll
    for (int i = 0; i < 32; i++) acc2[i] = 0ull;
#pragma unroll
    for (int ky = 0; ky < 3; ky++) {
        __syncthreads();
        for (int idx = tid; idx < E3_W_FLOATS; idx += 256) {
            int kx = idx >> 12, ci = (idx >> 6) & 63, o = idx & 63;
            sw[idx] = w[(o * 64 + ci) * 9 + ky * 3 + kx];
        }
        __syncthreads();
#pragma unroll
        for (int kx = 0; kx < 3; kx++) {
            for (int ci = 0; ci < 64; ci++) {
                const float* vb = &sIn[ci * (18 * E3_PITCH) + (r + ky) * E3_PITCH + 8 * h + kx];
                u64 v2[8];
#pragma unroll
                for (int j = 0; j < 8; j++) v2[j] = pack2(vb[j]);
                const ulonglong2* wp = (const ulonglong2*)&sw[(kx * 64 + ci) * 64 + og8 * 8];
                ulonglong2 wA = wp[0], wB = wp[1];
                u64 w2[4] = {wA.x, wA.y, wB.x, wB.y};
#pragma unroll
                for (int j = 0; j < 8; j++)
#pragma unroll
                    for (int o2 = 0; o2 < 4; o2++)
                        fma2(acc2[j * 4 + o2], v2[j], w2[o2]);
            }
        }
    }
    int oy = 16 * t_y + r, ox0 = 16 * t_x + 8 * h;
#pragma unroll
    for (int o2 = 0; o2 < 4; o2++) {
        int o = og8 * 8 + 2 * o2;
        float b0 = b[o], b1 = b[o + 1];
        float* op0 = ze + ((n * 64 + o) * 64 + oy) * 64 + ox0;
        float* op1 = op0 + 4096;
#pragma unroll
        for (int j = 0; j < 8; j++) {
            float2 t2 = unpack2(acc2[j * 4 + o2]);
            op0[j] = fmaxf(__fadd_rn(t2.x, b0), 0.f);
            op1[j] = fmaxf(__fadd_rn(t2.y, b1), 0.f);
        }
    }
}

// ===========================================================================
// VQ — GEMM-tiled, FROZEN chains; z stored DUPLICATED in smem so the
// broadcast operand is one aligned LDS.64 (no pack2 MOVs).
// ===========================================================================
#define VQ_ZP  132
#define VQ_ZP2 264
#define VQ_Z_FL   (64 * VQ_ZP2)        // 16896 (duplicated)
#define VQ_E_FL   (64 * VQ_ZP)         // 8448
#define VQ_SMEM_FL (VQ_Z_FL + VQ_E_FL + 128 + 128 + 128)
#define VQ_SMEM_B (VQ_SMEM_FL * 4)
__global__ __launch_bounds__(256, 2) void k_vq(const float* __restrict__ ze,
                                               const float* __restrict__ emb,
                                               float* __restrict__ zq) {
    extern __shared__ float sm[];
    float* sz   = sm;                        // [c][2*pos] duplicated
    float* se   = sm + VQ_Z_FL;              // [c][k]
    float* ssqz = sm + VQ_Z_FL + VQ_E_FL;
    float* snc  = ssqz + 128;
    int*   sbi  = (int*)(snc + 128);
    int tid = threadIdx.x;
    int pt = tid >> 4;
    int kt = tid & 15;

    int base = blockIdx.x * 128;
    int n = base >> 12;
    int rem = base & 4095;
    const float* zg = ze + n * 262144 + rem;

    for (int idx = tid; idx < 8192; idx += 256) {
        int c = idx >> 7, pos = idx & 127;
        float v = zg[c * 4096 + pos];
        *(float2*)&sz[c * VQ_ZP2 + 2 * pos] = make_float2(v, v);
    }
    __syncthreads();
    if (tid < 128) {
        float s = 0.f;
#pragma unroll
        for (int c = 0; c < 64; c++) {
            float z = sz[c * VQ_ZP2 + 2 * tid];
            s = __fadd_rn(s, __fmul_rn(z, z));
        }
        ssqz[tid] = s;
    }

    float best[8];
    int bi[8];
#pragma unroll
    for (int p = 0; p < 8; p++) { best[p] = 3.4028235e38f; bi[p] = 0; }

    for (int ch = 0; ch < 4; ch++) {
        int kc0 = ch * 128;
        __syncthreads();
        for (int idx = tid; idx < 8192; idx += 256) {
            int k = idx >> 6, c = idx & 63;
            se[c * VQ_ZP + k] = emb[(kc0 + k) * 64 + c];
        }
        __syncthreads();
        if (tid < 128) {
            float s = 0.f;
#pragma unroll
            for (int c = 0; c < 64; c++) {
                float e = se[c * VQ_ZP + tid];
                s = __fadd_rn(s, __fmul_rn(e, e));
            }
            snc[tid] = s;
        }
        u64 acc2[32];                  // [p8][j2:4], lanes = codes (2*j2, 2*j2+1)
#pragma unroll
        for (int i = 0; i < 32; i++) acc2[i] = 0ull;
        const float* zp = sz + pt * 16;          // duplicated: 8 pos = 16 floats
        const float* ep = se + kt * 8;
        for (int c = 0; c < 64; c++) {
            const u64* zdp = (const u64*)(zp + c * VQ_ZP2);
            u64 z2[8];
#pragma unroll
            for (int p = 0; p < 8; p++) z2[p] = zdp[p];
            const ulonglong2* epp = (const ulonglong2*)(ep + c * VQ_ZP);
            ulonglong2 E0 = epp[0], E1 = epp[1];
            u64 e2v[4] = {E0.x, E0.y, E1.x, E1.y};
#pragma unroll
            for (int p = 0; p < 8; p++)
#pragma unroll
                for (int j2 = 0; j2 < 4; j2++)
                    fma2(acc2[p * 4 + j2], z2[p], e2v[j2]);
        }
        __syncthreads();
#pragma unroll
        for (int p = 0; p < 8; p++) {
            float sq = ssqz[pt * 8 + p];
#pragma unroll
            for (int j2 = 0; j2 < 4; j2++) {
                float2 d = unpack2(acc2[p * 4 + j2]);
                int k0i = kc0 + kt * 8 + 2 * j2;
                float q0 = __fadd_rn(__fsub_rn(sq, __fmul_rn(2.f, d.x)), snc[kt * 8 + 2 * j2]);
                if (q0 < best[p]) { best[p] = q0; bi[p] = k0i; }
                float q1 = __fadd_rn(__fsub_rn(sq, __fmul_rn(2.f, d.y)), snc[kt * 8 + 2 * j2 + 1]);
                if (q1 < best[p]) { best[p] = q1; bi[p] = k0i + 1; }
            }
        }
    }
#pragma unroll
    for (int p = 0; p < 8; p++) {
        float bv = best[p];
        int ii = bi[p];
#pragma unroll
        for (int off = 1; off < 16; off <<= 1) {
            float ov = __shfl_xor_sync(0xffffffffu, bv, off);
            int oi = __shfl_xor_sync(0xffffffffu, ii, off);
            if (ov < bv || (ov == bv && oi < ii)) { bv = ov; ii = oi; }
        }
        if (kt == 0) sbi[pt * 8 + p] = ii;
    }
    __syncthreads();
    {
        int pos = tid & 127;
        int c0 = (tid >> 7) * 32;
        int code = sbi[pos];
        const float* eg = emb + code * 64;
        float* zqp = zq + n * 262144 + rem + pos;
        float* dp = g_dec + n * 262144 + rem + pos;
#pragma unroll
        for (int c = 0; c < 32; c++) {
            int cc = c0 + c;
            float e = __ldg(eg + cc);
            float z = sz[cc * VQ_ZP2 + 2 * pos];
            zqp[cc * 4096] = e;
            dp[cc * 4096] = __fadd_rn(z, __fsub_rn(e, z));
        }
    }
}

// ===========================================================================
// DECODER (1e-3 tolerance — f32x2 with DUPLICATED input tiles, no MOVs)
// ===========================================================================

// d1: conv_t 64->32, k3 s1 p1. Input tile duplicated: [ci][34][2*19].
#define D1_CI 16
#define D1_IN_FL (D1_CI * 34 * 38)    // 20672 (duplicated)
#define D1_W_FL  (D1_CI * 9 * 32)     // 4608
#define D1_SMEM_B ((D1_IN_FL + D1_W_FL) * 4)
__global__ __launch_bounds__(256, 2) void k_d1(const float* __restrict__ w,
                                               const float* __restrict__ b) {
    extern __shared__ float sm[];
    float* sIn = sm;             // duplicated pairs
    float* sw  = sm + D1_IN_FL;
    int tid = threadIdx.x;
    int kt = tid & 3;
    int pt = tid >> 2;
    int r = pt >> 1, h = pt & 1;
    int ty = blockIdx.x >> 2, tx = blockIdx.x & 3;
    int n = blockIdx.y;
    int iy0 = 32 * ty - 1, ix0 = 16 * tx - 1;
    u64 acc2[32];
#pragma unroll
    for (int i = 0; i < 32; i++) acc2[i] = 0ull;
    for (int cc = 0; cc < 4; cc++) {
        int ci0 = cc * D1_CI;
        __syncthreads();
        for (int idx = tid; idx < D1_CI * 34 * 18; idx += 256) {
            int ci = idx / 612, rr = idx - ci * 612;
            int iy = rr / 18, ix = rr - iy * 18;
            int gy = iy0 + iy, gx = ix0 + ix;
            float v = 0.f;
            if (gy >= 0 && gy < 64 && gx >= 0 && gx < 64)
                v = g_dec[((n * 64 + ci0 + ci) * 64 + gy) * 64 + gx];
            *(float2*)&sIn[ci * 1292 + iy * 38 + 2 * ix] = make_float2(v, v);
        }
        for (int idx = tid; idx < D1_W_FL; idx += 256) {
            int ci = idx / 288, rr = idx - ci * 288;
            int tap = rr >> 5, o = rr & 31;
            sw[(ci * 9 + tap) * 32 + o] = w[((ci0 + ci) * 32 + o) * 9 + (8 - tap)];
        }
        __syncthreads();
#pragma unroll 4
        for (int ci = 0; ci < D1_CI; ci++) {
#pragma unroll
            for (int ky = 0; ky < 3; ky++) {
                const u64* vp = (const u64*)&sIn[ci * 1292 + (r + ky) * 38 + 16 * h];
                u64 v2[10];
#pragma unroll
                for (int i = 0; i < 10; i++) v2[i] = vp[i];
#pragma unroll
                for (int kx = 0; kx < 3; kx++) {
                    const ulonglong2* wp = (const ulonglong2*)&sw[(ci * 9 + ky * 3 + kx) * 32 + kt * 8];
                    ulonglong2 wA = wp[0], wB = wp[1];
                    u64 w2[4] = {wA.x, wA.y, wB.x, wB.y};
#pragma unroll
                    for (int j = 0; j < 8; j++)
#pragma unroll
                        for (int o2 = 0; o2 < 4; o2++)
                            fma2(acc2[j * 4 + o2], v2[kx + j], w2[o2]);
                }
            }
        }
    }
    int oy = 32 * ty + r, ox0 = 16 * tx + 8 * h;
#pragma unroll
    for (int o2 = 0; o2 < 4; o2++) {
        int o = kt * 8 + 2 * o2;
        float b0 = b[o], b1 = b[o + 1];
        float* op0 = g_d1 + ((n * 32 + o) * 64 + oy) * 64 + ox0;
        float* op1 = op0 + 4096;
#pragma unroll
        for (int j = 0; j < 8; j++) {
            float2 t2 = unpack2(acc2[j * 4 + o2]);
            op0[j] = fmaxf(t2.x + b0, 0.f);
            op1[j] = fmaxf(t2.y + b1, 0.f);
        }
    }
}

// d2: conv_t 32->64, k4 s2 p1. Parity-plane GEMM; input tile duplicated.
#define D2_IN_FL (32 * 17 * 36)   // 19584 (duplicated)
#define D2_W_FL  (4 * 32 * 64)    // 8192
#define D2_SMEM_B ((D2_IN_FL + D2_W_FL) * 4)
__global__ __launch_bounds__(256, 2) void k_d2(const float* __restrict__ w,
                                               const float* __restrict__ b) {
    extern __shared__ float sm[];
    float* sIn = sm;             // [ci][17][2*18] duplicated
    float* sw  = sm + D2_IN_FL;
    int tid = threadIdx.x;
    int kt = tid & 7;
    int pt = tid >> 3;
    int Yr = pt >> 1, h = pt & 1;
    int bx = blockIdx.x;
    int pe = bx >> 4;
    int e = pe >> 1, f = pe & 1;
    int tile = bx & 15;
    int tY = tile >> 2, tX = tile & 3;
    int n = blockIdx.y;
    int py = 1 - e, px = 1 - f;
    int iy0 = 16 * tY + e - 1, ix0 = 16 * tX + f - 1;
    for (int idx = tid; idx < 32 * 17 * 17; idx += 256) {
        int ci = idx / 289, rr = idx - ci * 289;
        int iy = rr / 17, ix = rr - iy * 17;
        int gy = iy0 + iy, gx = ix0 + ix;
        float v = 0.f;
        if (gy >= 0 && gy < 64 && gx >= 0 && gx < 64)
            v = g_d1[((n * 32 + ci) * 64 + gy) * 64 + gx];
        *(float2*)&sIn[ci * 612 + iy * 36 + 2 * ix] = make_float2(v, v);
    }
    for (int idx = tid; idx < D2_W_FL; idx += 256) {
        int t4 = idx >> 11, ci = (idx >> 6) & 31, o = idx & 63;
        int tky = t4 >> 1, tkx = t4 & 1;
        sw[idx] = w[(ci * 64 + o) * 16 + (py + 2 * tky) * 4 + (px + 2 * tkx)];
    }
    __syncthreads();
    u64 acc2[32];
#pragma unroll
    for (int i = 0; i < 32; i++) acc2[i] = 0ull;
#pragma unroll 4
    for (int ci = 0; ci < 32; ci++) {
        const u64* pa = (const u64*)&sIn[ci * 612 + (Yr + 1) * 36 + 16 * h];
        const u64* pb = pa - 18;
        u64 va2[9], vb2[9];
#pragma unroll
        for (int i = 0; i < 9; i++) { va2[i] = pa[i]; vb2[i] = pb[i]; }
#pragma unroll
        for (int tky = 0; tky < 2; tky++) {
#pragma unroll
            for (int tkx = 0; tkx < 2; tkx++) {
                int t4 = tky * 2 + tkx;
                const ulonglong2* wp = (const ulonglong2*)&sw[(t4 * 32 + ci) * 64 + kt * 8];
                ulonglong2 wA = wp[0], wB = wp[1];
                u64 w2[4] = {wA.x, wA.y, wB.x, wB.y};
#pragma unroll
                for (int j = 0; j < 8; j++) {
                    u64 v = tky ? vb2[j + 1 - tkx] : va2[j + 1 - tkx];
#pragma unroll
                    for (int o2 = 0; o2 < 4; o2++)
                        fma2(acc2[j * 4 + o2], v, w2[o2]);
                }
            }
        }
    }
    int y = 32 * tY + 2 * Yr + e;
    int xbase = 32 * tX + 16 * h + f;
#pragma unroll
    for (int o2 = 0; o2 < 4; o2++) {
        int o = kt * 8 + 2 * o2;
        float b0 = b[o], b1 = b[o + 1];
        float* op0 = g_d2 + ((n * 64 + o) * 128 + y) * 128 + xbase;
        float* op1 = op0 + 16384;
#pragma unroll
        for (int j = 0; j < 8; j++) {
            float2 t2 = unpack2(acc2[j * 4 + o2]);
            op0[2 * j] = fmaxf(t2.x + b0, 0.f);
            op1[2 * j] = fmaxf(t2.y + b1, 0.f);
        }
    }
}

// d3: conv_t 64->1, k4 s2 p1 -> x_hat (R10 proven version)
__global__ __launch_bounds__(256) void k_d3(const float* __restrict__ w,
                                            const float* __restrict__ b,
                                            float* __restrict__ xh) {
    __shared__ float sIn[6400];
    __shared__ float sw[1024];
    int tid = threadIdx.x;
    int sy = tid >> 4, sx = tid & 15;
    int tb = blockIdx.x;
    int tx = tb & 15, ty = tb >> 4;
    int n = blockIdx.y;
    int iy0 = 8 * ty - 1, ix0 = 8 * tx - 1;
    for (int e = tid; e < 6400; e += 256) {
        int ci = e / 100, r = e - ci * 100;
        int iy = r / 10, ix = r - iy * 10;
        int gy = iy0 + iy, gx = ix0 + ix;
        float v = 0.f;
        if (gy >= 0 && gy < 128 && gx >= 0 && gx < 128)
            v = g_d2[((n * 64 + ci) * 128 + gy) * 128 + gx];
        sIn[e] = v;
    }
    for (int e = tid; e < 1024; e += 256) sw[e] = w[e];
    __syncthreads();
    int y = 16 * ty + sy, x = 16 * tx + sx;
    int py = (y + 1) & 1, px = (x + 1) & 1;
    int iya = ((sy + 1 - py) >> 1) + 1, ixa = ((sx + 1 - px) >> 1) + 1;
    float acc = b[0];
#pragma unroll 8
    for (int ci = 0; ci < 64; ci++) {
#pragma unroll
        for (int t_y = 0; t_y < 2; t_y++) {
            int ky = py + 2 * t_y, iyl = iya - t_y;
#pragma unroll
            for (int t_x = 0; t_x < 2; t_x++) {
                int kx = px + 2 * t_x, ixl = ixa - t_x;
                acc = fmaf(sIn[ci * 100 + iyl * 10 + ixl], sw[ci * 16 + ky * 4 + kx], acc);
            }
        }
    }
    xh[n * 65536 + y * 256 + x] = acc;
}

// ---------------------------------------------------------------------------
extern "C" void kernel_launch(void* const* d_in, const int* in_sizes, int n_in,
                              void* d_out, int out_size) {
    const float* x   = (const float*)d_in[0];
    const float* e1w = (const float*)d_in[1];
    const float* e1b = (const float*)d_in[2];
    const float* e2w = (const float*)d_in[3];
    const float* e2b = (const float*)d_in[4];
    const float* e3w = (const float*)d_in[5];
    const float* e3b = (const float*)d_in[6];
    const float* emb = (const float*)d_in[7];
    const float* d1w = (const float*)d_in[8];
    const float* d1b = (const float*)d_in[9];
    const float* d2w = (const float*)d_in[10];
    const float* d2b = (const float*)d_in[11];
    const float* d3w = (const float*)d_in[12];
    const float* d3b = (const float*)d_in[13];
    float* out = (float*)d_out;
    float* ze = out + OFF_ZE;
    float* zq = out + OFF_ZQ;

    cudaFuncSetAttribute(k_e2, cudaFuncAttributeMaxDynamicSharedMemorySize, E2_SMEM_B);
    cudaFuncSetAttribute(k_e3, cudaFuncAttributeMaxDynamicSharedMemorySize, E3_SMEM_B);
    cudaFuncSetAttribute(k_vq, cudaFuncAttributeMaxDynamicSharedMemorySize, VQ_SMEM_B);
    cudaFuncSetAttribute(k_d1, cudaFuncAttributeMaxDynamicSharedMemorySize, D1_SMEM_B);
    cudaFuncSetAttribute(k_d2, cudaFuncAttributeMaxDynamicSharedMemorySize, D2_SMEM_B);

    k_e1<<<4096, 256>>>(x, e1w, e1b);
    k_e2<<<dim3(16, 64), 256, E2_SMEM_B>>>(e2w, e2b);
    k_e3<<<dim3(16, 64), 256, E3_SMEM_B>>>(e3w, e3b, ze);
    k_vq<<<2048, 256, VQ_SMEM_B>>>(ze, emb, zq);
    k_d1<<<dim3(8, 64), 256, D1_SMEM_B>>>(d1w, d1b);
    k_d2<<<dim3(64, 64), 256, D2_SMEM_B>>>(d2w, d2b);
    k_d3<<<dim3(256, 64), 256>>>(d3w, d3b, out);
}

// round 15
// speedup vs baseline: 1.0403x; 1.0403x over previous
#include <cuda_runtime.h>

// Output layout: x_hat (64*1*256*256) | ze (64*64*64*64) | zq (64*64*64*64)
#define OFF_ZE 4194304
#define OFF_ZQ 20971520

// Scratch (__device__ globals)
__device__ float g_h1[33554432];   // (64,32,128,128)
__device__ float g_h2[16777216];   // (64,64,64,64)
__device__ float g_dec[16777216];  // (64,64,64,64)
__device__ float g_d1[8388608];    // (64,32,64,64)
__device__ float g_d2[67108864];   // (64,64,128,128)

// ---- packed fp32x2 helpers (sm_103a FFMA2; each lane exact IEEE fmaf)
typedef unsigned long long u64;
__device__ __forceinline__ u64 pack2(float f) {
    unsigned u = __float_as_uint(f);
    u64 r;
    asm("mov.b64 %0, {%1, %1};" : "=l"(r) : "r"(u));
    return r;
}
__device__ __forceinline__ void fma2(u64& acc, u64 a, u64 b) {
    asm("fma.rn.f32x2 %0, %1, %2, %0;" : "+l"(acc) : "l"(a), "l"(b));
}
__device__ __forceinline__ float2 unpack2(u64 v) {
    unsigned lo, hi;
    asm("mov.b64 {%0, %1}, %2;" : "=r"(lo), "=r"(hi) : "l"(v));
    return make_float2(__uint_as_float(lo), __uint_as_float(hi));
}

// ===========================================================================
// ENCODER — bit-exact emulation of XLA-CPU/Eigen conv (FROZEN arithmetic)
// ===========================================================================

// e1: conv 1->32, k4 s2 p1. x(64,1,256,256) -> g_h1(64,32,128,128)
__global__ __launch_bounds__(256) void k_e1(const float* __restrict__ x,
                                            const float* __restrict__ w,
                                            const float* __restrict__ b) {
    __shared__ float sw[16][32];   // [tap][o]
    __shared__ float sb[32];
    int t = threadIdx.x;
    {
        int o = t & 31, tap = t >> 5;
        sw[tap][o] = w[o * 16 + tap];
        int e = t + 256; o = e & 31; tap = e >> 5;
        sw[tap][o] = w[o * 16 + tap];
    }
    if (t < 32) sb[t] = b[t];
    __syncthreads();
    int gid = blockIdx.x * 256 + t;
    int ox = gid & 127, oy = (gid >> 7) & 127, n = gid >> 14;
    float acc[32];
#pragma unroll
    for (int o = 0; o < 32; o++) acc[o] = 0.f;
    const float* xin = x + n * 65536;
#pragma unroll
    for (int ky = 0; ky < 4; ky++) {
        int iy = 2 * oy - 1 + ky;
        if (iy < 0 || iy >= 256) continue;
#pragma unroll
        for (int kx = 0; kx < 4; kx++) {
            int ix = 2 * ox - 1 + kx;
            if (ix < 0 || ix >= 256) continue;
            float v = xin[iy * 256 + ix];
#pragma unroll
            for (int o = 0; o < 32; o++) acc[o] = fmaf(v, sw[ky * 4 + kx][o], acc[o]);
        }
    }
    float* op = g_h1 + n * 524288 + oy * 128 + ox;
#pragma unroll
    for (int o = 0; o < 32; o++) op[o * 16384] = fmaxf(__fadd_rn(acc[o], sb[o]), 0.f);
}

// e2: conv 32->64, k4 s2 p1. g_h1 -> g_h2(64,64,64,64)   (R10 proven)
#define E2_PITCH 35
#define E2_IN_FLOATS (32 * 34 * E2_PITCH)
#define E2_W_FLOATS  (4 * 32 * 64)
#define E2_SMEM_B   ((E2_IN_FLOATS + E2_W_FLOATS) * 4)
__global__ __launch_bounds__(256, 1) void k_e2(const float* __restrict__ w,
                                               const float* __restrict__ b) {
    extern __shared__ float sm[];
    float* sIn = sm;                 // [ci][34][35]
    float* sw  = sm + E2_IN_FLOATS;  // [kx][ci][o]
    int tid = threadIdx.x;
    int og8 = tid >> 5;
    int sp = tid & 31;
    int r = sp >> 1, h = sp & 1;
    int t_y = blockIdx.x >> 2, t_x = blockIdx.x & 3;
    int n = blockIdx.y;
    int iy0 = 32 * t_y - 1, ix0 = 32 * t_x - 1;
    for (int idx = tid; idx < 32 * 34 * 34; idx += 256) {
        int ci = idx / 1156, rr = idx - ci * 1156;
        int iy = rr / 34, ix = rr - iy * 34;
        int gy = iy0 + iy, gx = ix0 + ix;
        float v = 0.f;
        if (gy >= 0 && gy < 128 && gx >= 0 && gx < 128)
            v = g_h1[((n * 32 + ci) * 128 + gy) * 128 + gx];
        sIn[ci * (34 * E2_PITCH) + iy * E2_PITCH + ix] = v;
    }
    float acc[64];
#pragma unroll
    for (int i = 0; i < 64; i++) acc[i] = 0.f;
#pragma unroll
    for (int ky = 0; ky < 4; ky++) {
        __syncthreads();
        for (int idx = tid; idx < E2_W_FLOATS; idx += 256) {
            int kx = idx >> 11, ci = (idx >> 6) & 31, o = idx & 63;
            sw[idx] = w[(o * 32 + ci) * 16 + ky * 4 + kx];
        }
        __syncthreads();
#pragma unroll
        for (int kx = 0; kx < 4; kx++) {
            for (int ci = 0; ci < 32; ci++) {
                const float* vb = &sIn[ci * (34 * E2_PITCH) + (2 * r + ky) * E2_PITCH + 16 * h + kx];
                float v[8];
#pragma unroll
                for (int j = 0; j < 8; j++) v[j] = vb[2 * j];
                const float4* wp = (const float4*)&sw[(kx * 32 + ci) * 64 + og8 * 8];
                float4 w0 = wp[0], w1 = wp[1];
                float wv[8] = {w0.x, w0.y, w0.z, w0.w, w1.x, w1.y, w1.z, w1.w};
#pragma unroll
                for (int j = 0; j < 8; j++)
#pragma unroll
                    for (int oo = 0; oo < 8; oo++)
                        acc[j * 8 + oo] = fmaf(v[j], wv[oo], acc[j * 8 + oo]);
            }
        }
    }
    int oy = 16 * t_y + r, ox0 = 16 * t_x + 8 * h;
#pragma unroll
    for (int oo = 0; oo < 8; oo++) {
        int o = og8 * 8 + oo;
        float bb = b[o];
        float* op = g_h2 + ((n * 64 + o) * 64 + oy) * 64 + ox0;
#pragma unroll
        for (int j = 0; j < 8; j++)
            op[j] = fmaxf(__fadd_rn(acc[j * 8 + oo], bb), 0.f);
    }
}

// e3: conv 64->64, k3 s1 p1. g_h2 -> ze (d_out)   (R10 proven)
#define E3_PITCH 21
#define E3_IN_FLOATS (64 * 18 * E3_PITCH)
#define E3_W_FLOATS  (3 * 64 * 64)
#define E3_SMEM_B   ((E3_IN_FLOATS + E3_W_FLOATS) * 4)
__global__ __launch_bounds__(256, 1) void k_e3(const float* __restrict__ w,
                                               const float* __restrict__ b,
                                               float* __restrict__ ze) {
    extern __shared__ float sm[];
    float* sIn = sm;                 // [ci][18][21]
    float* sw  = sm + E3_IN_FLOATS;  // [kx][ci][o]
    int tid = threadIdx.x;
    int og8 = tid >> 5;
    int sp = tid & 31;
    int r = sp >> 1, h = sp & 1;
    int t_y = blockIdx.x >> 2, t_x = blockIdx.x & 3;
    int n = blockIdx.y;
    int iy0 = 16 * t_y - 1, ix0 = 16 * t_x - 1;
    for (int idx = tid; idx < 64 * 18 * 18; idx += 256) {
        int ci = idx / 324, rr = idx - ci * 324;
        int iy = rr / 18, ix = rr - iy * 18;
        int gy = iy0 + iy, gx = ix0 + ix;
        float v = 0.f;
        if (gy >= 0 && gy < 64 && gx >= 0 && gx < 64)
            v = g_h2[((n * 64 + ci) * 64 + gy) * 64 + gx];
        sIn[ci * (18 * E3_PITCH) + iy * E3_PITCH + ix] = v;
    }
    float acc[64];
#pragma unroll
    for (int i = 0; i < 64; i++) acc[i] = 0.f;
#pragma unroll
    for (int ky = 0; ky < 3; ky++) {
        __syncthreads();
        for (int idx = tid; idx < E3_W_FLOATS; idx += 256) {
            int kx = idx >> 12, ci = (idx >> 6) & 63, o = idx & 63;
            sw[idx] = w[(o * 64 + ci) * 9 + ky * 3 + kx];
        }
        __syncthreads();
#pragma unroll
        for (int kx = 0; kx < 3; kx++) {
            for (int ci = 0; ci < 64; ci++) {
                const float* vb = &sIn[ci * (18 * E3_PITCH) + (r + ky) * E3_PITCH + 8 * h + kx];
                float v[8];
#pragma unroll
                for (int j = 0; j < 8; j++) v[j] = vb[j];
                const float4* wp = (const float4*)&sw[(kx * 64 + ci) * 64 + og8 * 8];
                float4 w0 = wp[0], w1 = wp[1];
                float wv[8] = {w0.x, w0.y, w0.z, w0.w, w1.x, w1.y, w1.z, w1.w};
#pragma unroll
                for (int j = 0; j < 8; j++)
#pragma unroll
                    for (int oo = 0; oo < 8; oo++)
                        acc[j * 8 + oo] = fmaf(v[j], wv[oo], acc[j * 8 + oo]);
            }
        }
    }
    int oy = 16 * t_y + r, ox0 = 16 * t_x + 8 * h;
#pragma unroll
    for (int oo = 0; oo < 8; oo++) {
        int o = og8 * 8 + oo;
        float bb = b[o];
        float* op = ze + ((n * 64 + o) * 64 + oy) * 64 + ox0;
#pragma unroll
        for (int j = 0; j < 8; j++)
            op[j] = fmaxf(__fadd_rn(acc[j * 8 + oo], bb), 0.f);
    }
}

// ===========================================================================
// VQ — GEMM-tiled, FROZEN chains; f32x2 packs adjacent code pairs (R13
// measured 444us: codes pre-packed from smem, z packed via 8 pack2/c).
// ===========================================================================
#define VQ_ZP 132
#define VQ_Z_FL   (64 * VQ_ZP)
#define VQ_E_FL   (64 * VQ_ZP)
#define VQ_SMEM_FL (VQ_Z_FL + VQ_E_FL + 128 + 128 + 128)
#define VQ_SMEM_B (VQ_SMEM_FL * 4)
__global__ __launch_bounds__(256, 2) void k_vq(const float* __restrict__ ze,
                                               const float* __restrict__ emb,
                                               float* __restrict__ zq) {
    extern __shared__ float sm[];
    float* sz   = sm;
    float* se   = sm + VQ_Z_FL;
    float* ssqz = sm + VQ_Z_FL + VQ_E_FL;
    float* snc  = ssqz + 128;
    int*   sbi  = (int*)(snc + 128);
    int tid = threadIdx.x;
    int pt = tid >> 4;
    int kt = tid & 15;

    int base = blockIdx.x * 128;
    int n = base >> 12;
    int rem = base & 4095;
    const float* zg = ze + n * 262144 + rem;

    for (int idx = tid; idx < 8192; idx += 256) {
        int c = idx >> 7, pos = idx & 127;
        sz[c * VQ_ZP + pos] = zg[c * 4096 + pos];
    }
    __syncthreads();
    if (tid < 128) {
        float s = 0.f;
#pragma unroll
        for (int c = 0; c < 64; c++) {
            float z = sz[c * VQ_ZP + tid];
            s = __fadd_rn(s, __fmul_rn(z, z));
        }
        ssqz[tid] = s;
    }

    float best[8];
    int bi[8];
#pragma unroll
    for (int p = 0; p < 8; p++) { best[p] = 3.4028235e38f; bi[p] = 0; }

    for (int ch = 0; ch < 4; ch++) {
        int kc0 = ch * 128;
        __syncthreads();
        for (int idx = tid; idx < 8192; idx += 256) {
            int k = idx >> 6, c = idx & 63;
            se[c * VQ_ZP + k] = emb[(kc0 + k) * 64 + c];
        }
        __syncthreads();
        if (tid < 128) {
            float s = 0.f;
#pragma unroll
            for (int c = 0; c < 64; c++) {
                float e = se[c * VQ_ZP + tid];
                s = __fadd_rn(s, __fmul_rn(e, e));
            }
            snc[tid] = s;
        }
        u64 acc2[32];                  // [p8][j2:4], lanes = codes (2*j2, 2*j2+1)
#pragma unroll
        for (int i = 0; i < 32; i++) acc2[i] = 0ull;
        const float* zp = sz + pt * 8;
        const float* ep = se + kt * 8;
        for (int c = 0; c < 64; c++) {
            float4 z0 = *(const float4*)(zp + c * VQ_ZP);
            float4 z1 = *(const float4*)(zp + c * VQ_ZP + 4);
            u64 z2[8];
            z2[0] = pack2(z0.x); z2[1] = pack2(z0.y);
            z2[2] = pack2(z0.z); z2[3] = pack2(z0.w);
            z2[4] = pack2(z1.x); z2[5] = pack2(z1.y);
            z2[6] = pack2(z1.z); z2[7] = pack2(z1.w);
            const ulonglong2* epp = (const ulonglong2*)(ep + c * VQ_ZP);
            ulonglong2 E0 = epp[0], E1 = epp[1];
            u64 e2v[4] = {E0.x, E0.y, E1.x, E1.y};
#pragma unroll
            for (int p = 0; p < 8; p++)
#pragma unroll
                for (int j2 = 0; j2 < 4; j2++)
                    fma2(acc2[p * 4 + j2], z2[p], e2v[j2]);
        }
        __syncthreads();
#pragma unroll
        for (int p = 0; p < 8; p++) {
            float sq = ssqz[pt * 8 + p];
#pragma unroll
            for (int j2 = 0; j2 < 4; j2++) {
                float2 d = unpack2(acc2[p * 4 + j2]);
                int k0i = kc0 + kt * 8 + 2 * j2;
                float q0 = __fadd_rn(__fsub_rn(sq, __fmul_rn(2.f, d.x)), snc[kt * 8 + 2 * j2]);
                if (q0 < best[p]) { best[p] = q0; bi[p] = k0i; }
                float q1 = __fadd_rn(__fsub_rn(sq, __fmul_rn(2.f, d.y)), snc[kt * 8 + 2 * j2 + 1]);
                if (q1 < best[p]) { best[p] = q1; bi[p] = k0i + 1; }
            }
        }
    }
#pragma unroll
    for (int p = 0; p < 8; p++) {
        float bv = best[p];
        int ii = bi[p];
#pragma unroll
        for (int off = 1; off < 16; off <<= 1) {
            float ov = __shfl_xor_sync(0xffffffffu, bv, off);
            int oi = __shfl_xor_sync(0xffffffffu, ii, off);
            if (ov < bv || (ov == bv && oi < ii)) { bv = ov; ii = oi; }
        }
        if (kt == 0) sbi[pt * 8 + p] = ii;
    }
    __syncthreads();
    {
        int pos = tid & 127;
        int c0 = (tid >> 7) * 32;
        int code = sbi[pos];
        const float* eg = emb + code * 64;
        float* zqp = zq + n * 262144 + rem + pos;
        float* dp = g_dec + n * 262144 + rem + pos;
#pragma unroll
        for (int c = 0; c < 32; c++) {
            int cc = c0 + c;
            float e = __ldg(eg + cc);
            float z = sz[cc * VQ_ZP + pos];
            zqp[cc * 4096] = e;
            dp[cc * 4096] = __fadd_rn(z, __fsub_rn(e, z));
        }
    }
}

// ===========================================================================
// DECODER (1e-3 tolerance — R10 proven kernels)
// ===========================================================================

// d1: conv_t 64->32, k3 s1 p1 == conv with flipped/swapped weights.
#define D1_CI 16
#define D1_IN_FL (D1_CI * 34 * 19)
#define D1_W_FL  (D1_CI * 9 * 32)
#define D1_SMEM_B ((D1_IN_FL + D1_W_FL) * 4)
__global__ __launch_bounds__(256, 2) void k_d1(const float* __restrict__ w,
                                               const float* __restrict__ b) {
    extern __shared__ float sm[];
    float* sIn = sm;
    float* sw  = sm + D1_IN_FL;
    int tid = threadIdx.x;
    int kt = tid & 3;
    int pt = tid >> 2;
    int r = pt >> 1, h = pt & 1;
    int ty = blockIdx.x >> 2, tx = blockIdx.x & 3;
    int n = blockIdx.y;
    int iy0 = 32 * ty - 1, ix0 = 16 * tx - 1;
    float acc[64];
#pragma unroll
    for (int i = 0; i < 64; i++) acc[i] = 0.f;
    for (int cc = 0; cc < 4; cc++) {
        int ci0 = cc * D1_CI;
        __syncthreads();
        for (int idx = tid; idx < D1_CI * 34 * 18; idx += 256) {
            int ci = idx / 612, rr = idx - ci * 612;
            int iy = rr / 18, ix = rr - iy * 18;
            int gy = iy0 + iy, gx = ix0 + ix;
            float v = 0.f;
            if (gy >= 0 && gy < 64 && gx >= 0 && gx < 64)
                v = g_dec[((n * 64 + ci0 + ci) * 64 + gy) * 64 + gx];
            sIn[ci * 646 + iy * 19 + ix] = v;
        }
        for (int idx = tid; idx < D1_W_FL; idx += 256) {
            int ci = idx / 288, rr = idx - ci * 288;
            int tap = rr >> 5, o = rr & 31;
            sw[(ci * 9 + tap) * 32 + o] = w[((ci0 + ci) * 32 + o) * 9 + (8 - tap)];
        }
        __syncthreads();
#pragma unroll 4
        for (int ci = 0; ci < D1_CI; ci++) {
#pragma unroll
            for (int ky = 0; ky < 3; ky++) {
                const float* vp = &sIn[ci * 646 + (r + ky) * 19 + 8 * h];
                float v[10];
#pragma unroll
                for (int i = 0; i < 10; i++) v[i] = vp[i];
#pragma unroll
                for (int kx = 0; kx < 3; kx++) {
                    const float4* wp = (const float4*)&sw[(ci * 9 + ky * 3 + kx) * 32 + kt * 8];
                    float4 w0 = wp[0], w1 = wp[1];
                    float wv[8] = {w0.x, w0.y, w0.z, w0.w, w1.x, w1.y, w1.z, w1.w};
#pragma unroll
                    for (int j = 0; j < 8; j++) {
                        float vv = v[kx + j];
#pragma unroll
                        for (int oo = 0; oo < 8; oo++)
                            acc[j * 8 + oo] = fmaf(vv, wv[oo], acc[j * 8 + oo]);
                    }
                }
            }
        }
    }
    int oy = 32 * ty + r, ox0 = 16 * tx + 8 * h;
#pragma unroll
    for (int oo = 0; oo < 8; oo++) {
        int o = kt * 8 + oo;
        float bb = b[o];
        float* op = g_d1 + ((n * 32 + o) * 64 + oy) * 64 + ox0;
#pragma unroll
        for (int j = 0; j < 8; j++)
            op[j] = fmaxf(acc[j * 8 + oo] + bb, 0.f);
    }
}

// d2: conv_t 32->64, k4 s2 p1. Parity-plane GEMM (R10 proven).
#define D2_IN_FL (32 * 17 * 18)
#define D2_W_FL  (4 * 32 * 64)
#define D2_SMEM_B ((D2_IN_FL + D2_W_FL) * 4)
__global__ __launch_bounds__(256, 2) void k_d2(const float* __restrict__ w,
                                               const float* __restrict__ b) {
    extern __shared__ float sm[];
    float* sIn = sm;
    float* sw  = sm + D2_IN_FL;
    int tid = threadIdx.x;
    int kt = tid & 7;
    int pt = tid >> 3;
    int Yr = pt >> 1, h = pt & 1;
    int bx = blockIdx.x;
    int pe = bx >> 4;
    int e = pe >> 1, f = pe & 1;
    int tile = bx & 15;
    int tY = tile >> 2, tX = tile & 3;
    int n = blockIdx.y;
    int py = 1 - e, px = 1 - f;
    int iy0 = 16 * tY + e - 1, ix0 = 16 * tX + f - 1;
    for (int idx = tid; idx < 32 * 17 * 17; idx += 256) {
        int ci = idx / 289, rr = idx - ci * 289;
        int iy = rr / 17, ix = rr - iy * 17;
        int gy = iy0 + iy, gx = ix0 + ix;
        float v = 0.f;
        if (gy >= 0 && gy < 64 && gx >= 0 && gx < 64)
            v = g_d1[((n * 32 + ci) * 64 + gy) * 64 + gx];
        sIn[ci * 306 + iy * 18 + ix] = v;
    }
    for (int idx = tid; idx < D2_W_FL; idx += 256) {
        int t4 = idx >> 11, ci = (idx >> 6) & 31, o = idx & 63;
        int tky = t4 >> 1, tkx = t4 & 1;
        sw[idx] = w[(ci * 64 + o) * 16 + (py + 2 * tky) * 4 + (px + 2 * tkx)];
    }
    __syncthreads();
    float acc[64];
#pragma unroll
    for (int i = 0; i < 64; i++) acc[i] = 0.f;
#pragma unroll 4
    for (int ci = 0; ci < 32; ci++) {
        const float* pa = &sIn[ci * 306 + (Yr + 1) * 18 + 8 * h];
        const float* pb = pa - 18;
        float va[9], vb[9];
#pragma unroll
        for (int i = 0; i < 9; i++) { va[i] = pa[i]; vb[i] = pb[i]; }
#pragma unroll
        for (int tky = 0; tky < 2; tky++) {
#pragma unroll
            for (int tkx = 0; tkx < 2; tkx++) {
                int t4 = tky * 2 + tkx;
                const float4* wp = (const float4*)&sw[(t4 * 32 + ci) * 64 + kt * 8];
                float4 w0 = wp[0], w1 = wp[1];
                float wv[8] = {w0.x, w0.y, w0.z, w0.w, w1.x, w1.y, w1.z, w1.w};
#pragma unroll
                for (int j = 0; j < 8; j++) {
                    float v = tky ? vb[j + 1 - tkx] : va[j + 1 - tkx];
#pragma unroll
                    for (int oo = 0; oo < 8; oo++)
                        acc[j * 8 + oo] = fmaf(v, wv[oo], acc[j * 8 + oo]);
                }
            }
        }
    }
    int y = 32 * tY + 2 * Yr + e;
    int xbase = 32 * tX + 16 * h + f;
#pragma unroll
    for (int oo = 0; oo < 8; oo++) {
        int o = kt * 8 + oo;
        float bb = b[o];
        float* op = g_d2 + ((n * 64 + o) * 128 + y) * 128 + xbase;
#pragma unroll
        for (int j = 0; j < 8; j++)
            op[2 * j] = fmaxf(acc[j * 8 + oo] + bb, 0.f);
    }
}

// d3: conv_t 64->1, k4 s2 p1 -> x_hat (R10 proven version)
__global__ __launch_bounds__(256) void k_d3(const float* __restrict__ w,
                                            const float* __restrict__ b,
                                            float* __restrict__ xh) {
    __shared__ float sIn[6400];
    __shared__ float sw[1024];
    int tid = threadIdx.x;
    int sy = tid >> 4, sx = tid & 15;
    int tb = blockIdx.x;
    int tx = tb & 15, ty = tb >> 4;
    int n = blockIdx.y;
    int iy0 = 8 * ty - 1, ix0 = 8 * tx - 1;
    for (int e = tid; e < 6400; e += 256) {
        int ci = e / 100, r = e - ci * 100;
        int iy = r / 10, ix = r - iy * 10;
        int gy = iy0 + iy, gx = ix0 + ix;
        float v = 0.f;
        if (gy >= 0 && gy < 128 && gx >= 0 && gx < 128)
            v = g_d2[((n * 64 + ci) * 128 + gy) * 128 + gx];
        sIn[e] = v;
    }
    for (int e = tid; e < 1024; e += 256) sw[e] = w[e];
    __syncthreads();
    int y = 16 * ty + sy, x = 16 * tx + sx;
    int py = (y + 1) & 1, px = (x + 1) & 1;
    int iya = ((sy + 1 - py) >> 1) + 1, ixa = ((sx + 1 - px) >> 1) + 1;
    float acc = b[0];
#pragma unroll 8
    for (int ci = 0; ci < 64; ci++) {
#pragma unroll
        for (int t_y = 0; t_y < 2; t_y++) {
            int ky = py + 2 * t_y, iyl = iya - t_y;
#pragma unroll
            for (int t_x = 0; t_x < 2; t_x++) {
                int kx = px + 2 * t_x, ixl = ixa - t_x;
                acc = fmaf(sIn[ci * 100 + iyl * 10 + ixl], sw[ci * 16 + ky * 4 + kx], acc);
            }
        }
    }
    xh[n * 65536 + y * 256 + x] = acc;
}

// ---------------------------------------------------------------------------
extern "C" void kernel_launch(void* const* d_in, const int* in_sizes, int n_in,
                              void* d_out, int out_size) {
    const float* x   = (const float*)d_in[0];
    const float* e1w = (const float*)d_in[1];
    const float* e1b = (const float*)d_in[2];
    const float* e2w = (const float*)d_in[3];
    const float* e2b = (const float*)d_in[4];
    const float* e3w = (const float*)d_in[5];
    const float* e3b = (const float*)d_in[6];
    const float* emb = (const float*)d_in[7];
    const float* d1w = (const float*)d_in[8];
    const float* d1b = (const float*)d_in[9];
    const float* d2w = (const float*)d_in[10];
    const float* d2b = (const float*)d_in[11];
    const float* d3w = (const float*)d_in[12];
    const float* d3b = (const float*)d_in[13];
    float* out = (float*)d_out;
    float* ze = out + OFF_ZE;
    float* zq = out + OFF_ZQ;

    cudaFuncSetAttribute(k_e2, cudaFuncAttributeMaxDynamicSharedMemorySize, E2_SMEM_B);
    cudaFuncSetAttribute(k_e3, cudaFuncAttributeMaxDynamicSharedMemorySize, E3_SMEM_B);
    cudaFuncSetAttribute(k_vq, cudaFuncAttributeMaxDynamicSharedMemorySize, VQ_SMEM_B);
    cudaFuncSetAttribute(k_d1, cudaFuncAttributeMaxDynamicSharedMemorySize, D1_SMEM_B);
    cudaFuncSetAttribute(k_d2, cudaFuncAttributeMaxDynamicSharedMemorySize, D2_SMEM_B);

    k_e1<<<4096, 256>>>(x, e1w, e1b);
    k_e2<<<dim3(16, 64), 256, E2_SMEM_B>>>(e2w, e2b);
    k_e3<<<dim3(16, 64), 256, E3_SMEM_B>>>(e3w, e3b, ze);
    k_vq<<<2048, 256, VQ_SMEM_B>>>(ze, emb, zq);
    k_d1<<<dim3(8, 64), 256, D1_SMEM_B>>>(d1w, d1b);
    k_d2<<<dim3(64, 64), 256, D2_SMEM_B>>>(d2w, d2b);
    k_d3<<<dim3(256, 64), 256>>>(d3w, d3b, out);
}

// round 16
// speedup vs baseline: 1.0416x; 1.0012x over previous
#include <cuda_runtime.h>

// Output layout: x_hat (64*1*256*256) | ze (64*64*64*64) | zq (64*64*64*64)
#define OFF_ZE 4194304
#define OFF_ZQ 20971520

// Scratch (__device__ globals)
__device__ float g_h1[33554432];   // (64,32,128,128)
__device__ float g_h2[16777216];   // (64,64,64,64)
__device__ float g_d1[8388608];    // (64,32,64,64)
__device__ float g_d2[67108864];   // (64,64,128,128)

// ---- packed fp32x2 helpers (sm_103a FFMA2; each lane exact IEEE fmaf)
typedef unsigned long long u64;
__device__ __forceinline__ u64 pack2(float f) {
    unsigned u = __float_as_uint(f);
    u64 r;
    asm("mov.b64 %0, {%1, %1};" : "=l"(r) : "r"(u));
    return r;
}
__device__ __forceinline__ void fma2(u64& acc, u64 a, u64 b) {
    asm("fma.rn.f32x2 %0, %1, %2, %0;" : "+l"(acc) : "l"(a), "l"(b));
}
__device__ __forceinline__ float2 unpack2(u64 v) {
    unsigned lo, hi;
    asm("mov.b64 {%0, %1}, %2;" : "=r"(lo), "=r"(hi) : "l"(v));
    return make_float2(__uint_as_float(lo), __uint_as_float(hi));
}

// ===========================================================================
// ENCODER — bit-exact emulation of XLA-CPU/Eigen conv (FROZEN arithmetic)
// ===========================================================================

// e1: conv 1->32, k4 s2 p1. x(64,1,256,256) -> g_h1(64,32,128,128)
__global__ __launch_bounds__(256) void k_e1(const float* __restrict__ x,
                                            const float* __restrict__ w,
                                            const float* __restrict__ b) {
    __shared__ float sw[16][32];   // [tap][o]
    __shared__ float sb[32];
    int t = threadIdx.x;
    {
        int o = t & 31, tap = t >> 5;
        sw[tap][o] = w[o * 16 + tap];
        int e = t + 256; o = e & 31; tap = e >> 5;
        sw[tap][o] = w[o * 16 + tap];
    }
    if (t < 32) sb[t] = b[t];
    __syncthreads();
    int gid = blockIdx.x * 256 + t;
    int ox = gid & 127, oy = (gid >> 7) & 127, n = gid >> 14;
    float acc[32];
#pragma unroll
    for (int o = 0; o < 32; o++) acc[o] = 0.f;
    const float* xin = x + n * 65536;
#pragma unroll
    for (int ky = 0; ky < 4; ky++) {
        int iy = 2 * oy - 1 + ky;
        if (iy < 0 || iy >= 256) continue;
#pragma unroll
        for (int kx = 0; kx < 4; kx++) {
            int ix = 2 * ox - 1 + kx;
            if (ix < 0 || ix >= 256) continue;
            float v = xin[iy * 256 + ix];
#pragma unroll
            for (int o = 0; o < 32; o++) acc[o] = fmaf(v, sw[ky * 4 + kx][o], acc[o]);
        }
    }
    float* op = g_h1 + n * 524288 + oy * 128 + ox;
#pragma unroll
    for (int o = 0; o < 32; o++) op[o * 16384] = fmaxf(__fadd_rn(acc[o], sb[o]), 0.f);
}

// e2: conv 32->64, k4 s2 p1. g_h1 -> g_h2(64,64,64,64)   (R10 proven)
#define E2_PITCH 35
#define E2_IN_FLOATS (32 * 34 * E2_PITCH)
#define E2_W_FLOATS  (4 * 32 * 64)
#define E2_SMEM_B   ((E2_IN_FLOATS + E2_W_FLOATS) * 4)
__global__ __launch_bounds__(256, 1) void k_e2(const float* __restrict__ w,
                                               const float* __restrict__ b) {
    extern __shared__ float sm[];
    float* sIn = sm;                 // [ci][34][35]
    float* sw  = sm + E2_IN_FLOATS;  // [kx][ci][o]
    int tid = threadIdx.x;
    int og8 = tid >> 5;
    int sp = tid & 31;
    int r = sp >> 1, h = sp & 1;
    int t_y = blockIdx.x >> 2, t_x = blockIdx.x & 3;
    int n = blockIdx.y;
    int iy0 = 32 * t_y - 1, ix0 = 32 * t_x - 1;
    for (int idx = tid; idx < 32 * 34 * 34; idx += 256) {
        int ci = idx / 1156, rr = idx - ci * 1156;
        int iy = rr / 34, ix = rr - iy * 34;
        int gy = iy0 + iy, gx = ix0 + ix;
        float v = 0.f;
        if (gy >= 0 && gy < 128 && gx >= 0 && gx < 128)
            v = g_h1[((n * 32 + ci) * 128 + gy) * 128 + gx];
        sIn[ci * (34 * E2_PITCH) + iy * E2_PITCH + ix] = v;
    }
    float acc[64];
#pragma unroll
    for (int i = 0; i < 64; i++) acc[i] = 0.f;
#pragma unroll
    for (int ky = 0; ky < 4; ky++) {
        __syncthreads();
        for (int idx = tid; idx < E2_W_FLOATS; idx += 256) {
            int kx = idx >> 11, ci = (idx >> 6) & 31, o = idx & 63;
            sw[idx] = w[(o * 32 + ci) * 16 + ky * 4 + kx];
        }
        __syncthreads();
#pragma unroll
        for (int kx = 0; kx < 4; kx++) {
            for (int ci = 0; ci < 32; ci++) {
                const float* vb = &sIn[ci * (34 * E2_PITCH) + (2 * r + ky) * E2_PITCH + 16 * h + kx];
                float v[8];
#pragma unroll
                for (int j = 0; j < 8; j++) v[j] = vb[2 * j];
                const float4* wp = (const float4*)&sw[(kx * 32 + ci) * 64 + og8 * 8];
                float4 w0 = wp[0], w1 = wp[1];
                float wv[8] = {w0.x, w0.y, w0.z, w0.w, w1.x, w1.y, w1.z, w1.w};
#pragma unroll
                for (int j = 0; j < 8; j++)
#pragma unroll
                    for (int oo = 0; oo < 8; oo++)
                        acc[j * 8 + oo] = fmaf(v[j], wv[oo], acc[j * 8 + oo]);
            }
        }
    }
    int oy = 16 * t_y + r, ox0 = 16 * t_x + 8 * h;
#pragma unroll
    for (int oo = 0; oo < 8; oo++) {
        int o = og8 * 8 + oo;
        float bb = b[o];
        float* op = g_h2 + ((n * 64 + o) * 64 + oy) * 64 + ox0;
#pragma unroll
        for (int j = 0; j < 8; j++)
            op[j] = fmaxf(__fadd_rn(acc[j * 8 + oo], bb), 0.f);
    }
}

// e3: conv 64->64, k3 s1 p1. g_h2 -> ze (d_out)   (R10 proven)
#define E3_PITCH 21
#define E3_IN_FLOATS (64 * 18 * E3_PITCH)
#define E3_W_FLOATS  (3 * 64 * 64)
#define E3_SMEM_B   ((E3_IN_FLOATS + E3_W_FLOATS) * 4)
__global__ __launch_bounds__(256, 1) void k_e3(const float* __restrict__ w,
                                               const float* __restrict__ b,
                                               float* __restrict__ ze) {
    extern __shared__ float sm[];
    float* sIn = sm;                 // [ci][18][21]
    float* sw  = sm + E3_IN_FLOATS;  // [kx][ci][o]
    int tid = threadIdx.x;
    int og8 = tid >> 5;
    int sp = tid & 31;
    int r = sp >> 1, h = sp & 1;
    int t_y = blockIdx.x >> 2, t_x = blockIdx.x & 3;
    int n = blockIdx.y;
    int iy0 = 16 * t_y - 1, ix0 = 16 * t_x - 1;
    for (int idx = tid; idx < 64 * 18 * 18; idx += 256) {
        int ci = idx / 324, rr = idx - ci * 324;
        int iy = rr / 18, ix = rr - iy * 18;
        int gy = iy0 + iy, gx = ix0 + ix;
        float v = 0.f;
        if (gy >= 0 && gy < 64 && gx >= 0 && gx < 64)
            v = g_h2[((n * 64 + ci) * 64 + gy) * 64 + gx];
        sIn[ci * (18 * E3_PITCH) + iy * E3_PITCH + ix] = v;
    }
    float acc[64];
#pragma unroll
    for (int i = 0; i < 64; i++) acc[i] = 0.f;
#pragma unroll
    for (int ky = 0; ky < 3; ky++) {
        __syncthreads();
        for (int idx = tid; idx < E3_W_FLOATS; idx += 256) {
            int kx = idx >> 12, ci = (idx >> 6) & 63, o = idx & 63;
            sw[idx] = w[(o * 64 + ci) * 9 + ky * 3 + kx];
        }
        __syncthreads();
#pragma unroll
        for (int kx = 0; kx < 3; kx++) {
            for (int ci = 0; ci < 64; ci++) {
                const float* vb = &sIn[ci * (18 * E3_PITCH) + (r + ky) * E3_PITCH + 8 * h + kx];
                float v[8];
#pragma unroll
                for (int j = 0; j < 8; j++) v[j] = vb[j];
                const float4* wp = (const float4*)&sw[(kx * 64 + ci) * 64 + og8 * 8];
                float4 w0 = wp[0], w1 = wp[1];
                float wv[8] = {w0.x, w0.y, w0.z, w0.w, w1.x, w1.y, w1.z, w1.w};
#pragma unroll
                for (int j = 0; j < 8; j++)
#pragma unroll
                    for (int oo = 0; oo < 8; oo++)
                        acc[j * 8 + oo] = fmaf(v[j], wv[oo], acc[j * 8 + oo]);
            }
        }
    }
    int oy = 16 * t_y + r, ox0 = 16 * t_x + 8 * h;
#pragma unroll
    for (int oo = 0; oo < 8; oo++) {
        int o = og8 * 8 + oo;
        float bb = b[o];
        float* op = ze + ((n * 64 + o) * 64 + oy) * 64 + ox0;
#pragma unroll
        for (int j = 0; j < 8; j++)
            op[j] = fmaxf(__fadd_rn(acc[j * 8 + oo], bb), 0.f);
    }
}

// ===========================================================================
// VQ — GEMM-tiled, FROZEN chains; f32x2 code pairs (R13/R15 proven, 444us).
// dec_in stream dropped: decoder reads zq directly (<=1ulp difference).
// ===========================================================================
#define VQ_ZP 132
#define VQ_Z_FL   (64 * VQ_ZP)
#define VQ_E_FL   (64 * VQ_ZP)
#define VQ_SMEM_FL (VQ_Z_FL + VQ_E_FL + 128 + 128 + 128)
#define VQ_SMEM_B (VQ_SMEM_FL * 4)
__global__ __launch_bounds__(256, 2) void k_vq(const float* __restrict__ ze,
                                               const float* __restrict__ emb,
                                               float* __restrict__ zq) {
    extern __shared__ float sm[];
    float* sz   = sm;
    float* se   = sm + VQ_Z_FL;
    float* ssqz = sm + VQ_Z_FL + VQ_E_FL;
    float* snc  = ssqz + 128;
    int*   sbi  = (int*)(snc + 128);
    int tid = threadIdx.x;
    int pt = tid >> 4;
    int kt = tid & 15;

    int base = blockIdx.x * 128;
    int n = base >> 12;
    int rem = base & 4095;
    const float* zg = ze + n * 262144 + rem;

    for (int idx = tid; idx < 8192; idx += 256) {
        int c = idx >> 7, pos = idx & 127;
        sz[c * VQ_ZP + pos] = zg[c * 4096 + pos];
    }
    __syncthreads();
    if (tid < 128) {
        float s = 0.f;
#pragma unroll
        for (int c = 0; c < 64; c++) {
            float z = sz[c * VQ_ZP + tid];
            s = __fadd_rn(s, __fmul_rn(z, z));
        }
        ssqz[tid] = s;
    }

    float best[8];
    int bi[8];
#pragma unroll
    for (int p = 0; p < 8; p++) { best[p] = 3.4028235e38f; bi[p] = 0; }

    for (int ch = 0; ch < 4; ch++) {
        int kc0 = ch * 128;
        __syncthreads();
        for (int idx = tid; idx < 8192; idx += 256) {
            int k = idx >> 6, c = idx & 63;
            se[c * VQ_ZP + k] = emb[(kc0 + k) * 64 + c];
        }
        __syncthreads();
        if (tid < 128) {
            float s = 0.f;
#pragma unroll
            for (int c = 0; c < 64; c++) {
                float e = se[c * VQ_ZP + tid];
                s = __fadd_rn(s, __fmul_rn(e, e));
            }
            snc[tid] = s;
        }
        u64 acc2[32];                  // [p8][j2:4], lanes = codes (2*j2, 2*j2+1)
#pragma unroll
        for (int i = 0; i < 32; i++) acc2[i] = 0ull;
        const float* zp = sz + pt * 8;
        const float* ep = se + kt * 8;
        for (int c = 0; c < 64; c++) {
            float4 z0 = *(const float4*)(zp + c * VQ_ZP);
            float4 z1 = *(const float4*)(zp + c * VQ_ZP + 4);
            u64 z2[8];
            z2[0] = pack2(z0.x); z2[1] = pack2(z0.y);
            z2[2] = pack2(z0.z); z2[3] = pack2(z0.w);
            z2[4] = pack2(z1.x); z2[5] = pack2(z1.y);
            z2[6] = pack2(z1.z); z2[7] = pack2(z1.w);
            const ulonglong2* epp = (const ulonglong2*)(ep + c * VQ_ZP);
            ulonglong2 E0 = epp[0], E1 = epp[1];
            u64 e2v[4] = {E0.x, E0.y, E1.x, E1.y};
#pragma unroll
            for (int p = 0; p < 8; p++)
#pragma unroll
                for (int j2 = 0; j2 < 4; j2++)
                    fma2(acc2[p * 4 + j2], z2[p], e2v[j2]);
        }
        __syncthreads();
#pragma unroll
        for (int p = 0; p < 8; p++) {
            float sq = ssqz[pt * 8 + p];
#pragma unroll
            for (int j2 = 0; j2 < 4; j2++) {
                float2 d = unpack2(acc2[p * 4 + j2]);
                int k0i = kc0 + kt * 8 + 2 * j2;
                float q0 = __fadd_rn(__fsub_rn(sq, __fmul_rn(2.f, d.x)), snc[kt * 8 + 2 * j2]);
                if (q0 < best[p]) { best[p] = q0; bi[p] = k0i; }
                float q1 = __fadd_rn(__fsub_rn(sq, __fmul_rn(2.f, d.y)), snc[kt * 8 + 2 * j2 + 1]);
                if (q1 < best[p]) { best[p] = q1; bi[p] = k0i + 1; }
            }
        }
    }
#pragma unroll
    for (int p = 0; p < 8; p++) {
        float bv = best[p];
        int ii = bi[p];
#pragma unroll
        for (int off = 1; off < 16; off <<= 1) {
            float ov = __shfl_xor_sync(0xffffffffu, bv, off);
            int oi = __shfl_xor_sync(0xffffffffu, ii, off);
            if (ov < bv || (ov == bv && oi < ii)) { bv = ov; ii = oi; }
        }
        if (kt == 0) sbi[pt * 8 + p] = ii;
    }
    __syncthreads();
    {
        int pos = tid & 127;
        int c0 = (tid >> 7) * 32;
        int code = sbi[pos];
        const float* eg = emb + code * 64;
        float* zqp = zq + n * 262144 + rem + pos;
#pragma unroll
        for (int c = 0; c < 32; c++) {
            int cc = c0 + c;
            zqp[cc * 4096] = __ldg(eg + cc);
        }
    }
}

// ===========================================================================
// DECODER (1e-3 tolerance — R10 proven d1/d2; d3 re-tiled)
// ===========================================================================

// d1: conv_t 64->32, k3 s1 p1 == conv with flipped/swapped weights.
// Reads zq directly (dec_in == zq to within 1 ulp; tolerance absorbs it).
#define D1_CI 16
#define D1_IN_FL (D1_CI * 34 * 19)
#define D1_W_FL  (D1_CI * 9 * 32)
#define D1_SMEM_B ((D1_IN_FL + D1_W_FL) * 4)
__global__ __launch_bounds__(256, 2) void k_d1(const float* __restrict__ dec,
                                               const float* __restrict__ w,
                                               const float* __restrict__ b) {
    extern __shared__ float sm[];
    float* sIn = sm;
    float* sw  = sm + D1_IN_FL;
    int tid = threadIdx.x;
    int kt = tid & 3;
    int pt = tid >> 2;
    int r = pt >> 1, h = pt & 1;
    int ty = blockIdx.x >> 2, tx = blockIdx.x & 3;
    int n = blockIdx.y;
    int iy0 = 32 * ty - 1, ix0 = 16 * tx - 1;
    float acc[64];
#pragma unroll
    for (int i = 0; i < 64; i++) acc[i] = 0.f;
    for (int cc = 0; cc < 4; cc++) {
        int ci0 = cc * D1_CI;
        __syncthreads();
        for (int idx = tid; idx < D1_CI * 34 * 18; idx += 256) {
            int ci = idx / 612, rr = idx - ci * 612;
            int iy = rr / 18, ix = rr - iy * 18;
            int gy = iy0 + iy, gx = ix0 + ix;
            float v = 0.f;
            if (gy >= 0 && gy < 64 && gx >= 0 && gx < 64)
                v = dec[((n * 64 + ci0 + ci) * 64 + gy) * 64 + gx];
            sIn[ci * 646 + iy * 19 + ix] = v;
        }
        for (int idx = tid; idx < D1_W_FL; idx += 256) {
            int ci = idx / 288, rr = idx - ci * 288;
            int tap = rr >> 5, o = rr & 31;
            sw[(ci * 9 + tap) * 32 + o] = w[((ci0 + ci) * 32 + o) * 9 + (8 - tap)];
        }
        __syncthreads();
#pragma unroll 4
        for (int ci = 0; ci < D1_CI; ci++) {
#pragma unroll
            for (int ky = 0; ky < 3; ky++) {
                const float* vp = &sIn[ci * 646 + (r + ky) * 19 + 8 * h];
                float v[10];
#pragma unroll
                for (int i = 0; i < 10; i++) v[i] = vp[i];
#pragma unroll
                for (int kx = 0; kx < 3; kx++) {
                    const float4* wp = (const float4*)&sw[(ci * 9 + ky * 3 + kx) * 32 + kt * 8];
                    float4 w0 = wp[0], w1 = wp[1];
                    float wv[8] = {w0.x, w0.y, w0.z, w0.w, w1.x, w1.y, w1.z, w1.w};
#pragma unroll
                    for (int j = 0; j < 8; j++) {
                        float vv = v[kx + j];
#pragma unroll
                        for (int oo = 0; oo < 8; oo++)
                            acc[j * 8 + oo] = fmaf(vv, wv[oo], acc[j * 8 + oo]);
                    }
                }
            }
        }
    }
    int oy = 32 * ty + r, ox0 = 16 * tx + 8 * h;
#pragma unroll
    for (int oo = 0; oo < 8; oo++) {
        int o = kt * 8 + oo;
        float bb = b[o];
        float* op = g_d1 + ((n * 32 + o) * 64 + oy) * 64 + ox0;
#pragma unroll
        for (int j = 0; j < 8; j++)
            op[j] = fmaxf(acc[j * 8 + oo] + bb, 0.f);
    }
}

// d2: conv_t 32->64, k4 s2 p1. Parity-plane GEMM (R10 proven).
#define D2_IN_FL (32 * 17 * 18)
#define D2_W_FL  (4 * 32 * 64)
#define D2_SMEM_B ((D2_IN_FL + D2_W_FL) * 4)
__global__ __launch_bounds__(256, 2) void k_d2(const float* __restrict__ w,
                                               const float* __restrict__ b) {
    extern __shared__ float sm[];
    float* sIn = sm;
    float* sw  = sm + D2_IN_FL;
    int tid = threadIdx.x;
    int kt = tid & 7;
    int pt = tid >> 3;
    int Yr = pt >> 1, h = pt & 1;
    int bx = blockIdx.x;
    int pe = bx >> 4;
    int e = pe >> 1, f = pe & 1;
    int tile = bx & 15;
    int tY = tile >> 2, tX = tile & 3;
    int n = blockIdx.y;
    int py = 1 - e, px = 1 - f;
    int iy0 = 16 * tY + e - 1, ix0 = 16 * tX + f - 1;
    for (int idx = tid; idx < 32 * 17 * 17; idx += 256) {
        int ci = idx / 289, rr = idx - ci * 289;
        int iy = rr / 17, ix = rr - iy * 17;
        int gy = iy0 + iy, gx = ix0 + ix;
        float v = 0.f;
        if (gy >= 0 && gy < 64 && gx >= 0 && gx < 64)
            v = g_d1[((n * 32 + ci) * 64 + gy) * 64 + gx];
        sIn[ci * 306 + iy * 18 + ix] = v;
    }
    for (int idx = tid; idx < D2_W_FL; idx += 256) {
        int t4 = idx >> 11, ci = (idx >> 6) & 31, o = idx & 63;
        int tky = t4 >> 1, tkx = t4 & 1;
        sw[idx] = w[(ci * 64 + o) * 16 + (py + 2 * tky) * 4 + (px + 2 * tkx)];
    }
    __syncthreads();
    float acc[64];
#pragma unroll
    for (int i = 0; i < 64; i++) acc[i] = 0.f;
#pragma unroll 4
    for (int ci = 0; ci < 32; ci++) {
        const float* pa = &sIn[ci * 306 + (Yr + 1) * 18 + 8 * h];
        const float* pb = pa - 18;
        float va[9], vb[9];
#pragma unroll
        for (int i = 0; i < 9; i++) { va[i] = pa[i]; vb[i] = pb[i]; }
#pragma unroll
        for (int tky = 0; tky < 2; tky++) {
#pragma unroll
            for (int tkx = 0; tkx < 2; tkx++) {
                int t4 = tky * 2 + tkx;
                const float4* wp = (const float4*)&sw[(t4 * 32 + ci) * 64 + kt * 8];
                float4 w0 = wp[0], w1 = wp[1];
                float wv[8] = {w0.x, w0.y, w0.z, w0.w, w1.x, w1.y, w1.z, w1.w};
#pragma unroll
                for (int j = 0; j < 8; j++) {
                    float v = tky ? vb[j + 1 - tkx] : va[j + 1 - tkx];
#pragma unroll
                    for (int oo = 0; oo < 8; oo++)
                        acc[j * 8 + oo] = fmaf(v, wv[oo], acc[j * 8 + oo]);
                }
            }
        }
    }
    int y = 32 * tY + 2 * Yr + e;
    int xbase = 32 * tX + 16 * h + f;
#pragma unroll
    for (int oo = 0; oo < 8; oo++) {
        int o = kt * 8 + oo;
        float bb = b[o];
        float* op = g_d2 + ((n * 64 + o) * 128 + y) * 128 + xbase;
#pragma unroll
        for (int j = 0; j < 8; j++)
            op[2 * j] = fmaxf(acc[j * 8 + oo] + bb, 0.f);
    }
}

// d3: conv_t 64->1, k4 s2 p1 -> x_hat.
// 256 thr, 32x32 out tile, thread = 4 same-parity outputs in one row.
// Per ci: 10 v-LDS + 1 w-LDS128 + 16 FMA (validated tap algebra from R12);
// smem 87 KB -> 2 CTAs/SM (fixes R12's 128-thread fill bottleneck).
#define D3_IN_FL (64 * 18 * 19)    // 21888
#define D3_W_FL  (4 * 64 * 4)      // 1024
#define D3_SMEM_B ((D3_IN_FL + D3_W_FL) * 4)
__global__ __launch_bounds__(256, 2) void k_d3(const float* __restrict__ w,
                                               const float* __restrict__ b,
                                               float* __restrict__ xh) {
    extern __shared__ float sm[];
    float* sIn = sm;               // [ci][18][19]
    float* swp = sm + D3_IN_FL;    // [p][ci][4]
    int tid = threadIdx.x;
    int p = tid >> 6;              // parity 0..3: e=p>>1, f=p&1
    int sub = tid & 63;
    int rr = sub >> 2;             // 0..15 (row within parity)
    int xq = sub & 3;              // 0..3 (x group of 4 outputs)
    int e = p >> 1, f = p & 1;
    int ty = blockIdx.x >> 3, tx = blockIdx.x & 7;
    int n = blockIdx.y;
    int iy0 = 16 * ty - 1, ix0 = 16 * tx - 1;
    for (int idx = tid; idx < 64 * 18 * 18; idx += 256) {
        int ci = idx / 324, r2 = idx - ci * 324;
        int iy = r2 / 18, ix = r2 - iy * 18;
        int gy = iy0 + iy, gx = ix0 + ix;
        float v = 0.f;
        if (gy >= 0 && gy < 128 && gx >= 0 && gx < 128)
            v = g_d2[((n * 64 + ci) * 128 + gy) * 128 + gx];
        sIn[ci * 342 + iy * 19 + ix] = v;
    }
    for (int idx = tid; idx < D3_W_FL; idx += 256) {
        int pp = idx >> 8;
        int ci = (idx >> 2) & 63;
        int t4 = idx & 3;
        int tyt = t4 >> 1, txt = t4 & 1;
        int pye = 1 - (pp >> 1), pxe = 1 - (pp & 1);
        swp[idx] = w[ci * 16 + (pye + 2 * tyt) * 4 + (pxe + 2 * txt)];
    }
    __syncthreads();
    float acc[4];
#pragma unroll
    for (int d = 0; d < 4; d++) acc[d] = 0.f;
    int rowA = rr + e + 1;
    int c0 = 4 * xq + f;
#pragma unroll 8
    for (int ci = 0; ci < 64; ci++) {
        const float* pa = &sIn[ci * 342 + rowA * 19 + c0];
        const float* pb = pa - 19;
        float va[5], vb[5];
#pragma unroll
        for (int i = 0; i < 5; i++) { va[i] = pa[i]; vb[i] = pb[i]; }
        float4 w4 = *(const float4*)&swp[(p * 64 + ci) * 4];
#pragma unroll
        for (int d = 0; d < 4; d++) {
            acc[d] = fmaf(va[d + 1], w4.x, acc[d]);
            acc[d] = fmaf(va[d],     w4.y, acc[d]);
            acc[d] = fmaf(vb[d + 1], w4.z, acc[d]);
            acc[d] = fmaf(vb[d],     w4.w, acc[d]);
        }
    }
    float bb = b[0];
    int y = 32 * ty + 2 * rr + e;
    float* op = xh + n * 65536 + y * 256 + 32 * tx + 8 * xq + f;
#pragma unroll
    for (int d = 0; d < 4; d++)
        op[2 * d] = acc[d] + bb;
}

// ---------------------------------------------------------------------------
extern "C" void kernel_launch(void* const* d_in, const int* in_sizes, int n_in,
                              void* d_out, int out_size) {
    const float* x   = (const float*)d_in[0];
    const float* e1w = (const float*)d_in[1];
    const float* e1b = (const float*)d_in[2];
    const float* e2w = (const float*)d_in[3];
    const float* e2b = (const float*)d_in[4];
    const float* e3w = (const float*)d_in[5];
    const float* e3b = (const float*)d_in[6];
    const float* emb = (const float*)d_in[7];
    const float* d1w = (const float*)d_in[8];
    const float* d1b = (const float*)d_in[9];
    const float* d2w = (const float*)d_in[10];
    const float* d2b = (const float*)d_in[11];
    const float* d3w = (const float*)d_in[12];
    const float* d3b = (const float*)d_in[13];
    float* out = (float*)d_out;
    float* ze = out + OFF_ZE;
    float* zq = out + OFF_ZQ;

    cudaFuncSetAttribute(k_e2, cudaFuncAttributeMaxDynamicSharedMemorySize, E2_SMEM_B);
    cudaFuncSetAttribute(k_e3, cudaFuncAttributeMaxDynamicSharedMemorySize, E3_SMEM_B);
    cudaFuncSetAttribute(k_vq, cudaFuncAttributeMaxDynamicSharedMemorySize, VQ_SMEM_B);
    cudaFuncSetAttribute(k_d1, cudaFuncAttributeMaxDynamicSharedMemorySize, D1_SMEM_B);
    cudaFuncSetAttribute(k_d2, cudaFuncAttributeMaxDynamicSharedMemorySize, D2_SMEM_B);
    cudaFuncSetAttribute(k_d3, cudaFuncAttributeMaxDynamicSharedMemorySize, D3_SMEM_B);

    k_e1<<<4096, 256>>>(x, e1w, e1b);
    k_e2<<<dim3(16, 64), 256, E2_SMEM_B>>>(e2w, e2b);
    k_e3<<<dim3(16, 64), 256, E3_SMEM_B>>>(e3w, e3b, ze);
    k_vq<<<2048, 256, VQ_SMEM_B>>>(ze, emb, zq);
    k_d1<<<dim3(8, 64), 256, D1_SMEM_B>>>(zq, d1w, d1b);
    k_d2<<<dim3(64, 64), 256, D2_SMEM_B>>>(d2w, d2b);
    k_d3<<<dim3(64, 64), 256, D3_SMEM_B>>>(d3w, d3b, out);
}

// round 17
// speedup vs baseline: 1.0576x; 1.0154x over previous
#include <cuda_runtime.h>

// Output layout: x_hat (64*1*256*256) | ze (64*64*64*64) | zq (64*64*64*64)
#define OFF_ZE 4194304
#define OFF_ZQ 20971520

// Scratch (__device__ globals)
__device__ float g_h1[33554432];   // (64,32,128,128)
__device__ float g_h2[16777216];   // (64,64,64,64)
__device__ float g_d1[8388608];    // (64,32,64,64)
__device__ float g_d2[67108864];   // (64,64,128,128)

// ---- packed fp32x2 helpers (sm_103a FFMA2; each lane exact IEEE fmaf)
typedef unsigned long long u64;
__device__ __forceinline__ u64 pack2(float f) {
    unsigned u = __float_as_uint(f);
    u64 r;
    asm("mov.b64 %0, {%1, %1};" : "=l"(r) : "r"(u));
    return r;
}
__device__ __forceinline__ void fma2(u64& acc, u64 a, u64 b) {
    asm("fma.rn.f32x2 %0, %1, %2, %0;" : "+l"(acc) : "l"(a), "l"(b));
}
__device__ __forceinline__ float2 unpack2(u64 v) {
    unsigned lo, hi;
    asm("mov.b64 {%0, %1}, %2;" : "=r"(lo), "=r"(hi) : "l"(v));
    return make_float2(__uint_as_float(lo), __uint_as_float(hi));
}

// ===========================================================================
// ENCODER — bit-exact emulation of XLA-CPU/Eigen conv (FROZEN arithmetic)
// ===========================================================================

// e1: conv 1->32, k4 s2 p1. x(64,1,256,256) -> g_h1(64,32,128,128)
__global__ __launch_bounds__(256) void k_e1(const float* __restrict__ x,
                                            const float* __restrict__ w,
                                            const float* __restrict__ b) {
    __shared__ float sw[16][32];   // [tap][o]
    __shared__ float sb[32];
    int t = threadIdx.x;
    {
        int o = t & 31, tap = t >> 5;
        sw[tap][o] = w[o * 16 + tap];
        int e = t + 256; o = e & 31; tap = e >> 5;
        sw[tap][o] = w[o * 16 + tap];
    }
    if (t < 32) sb[t] = b[t];
    __syncthreads();
    int gid = blockIdx.x * 256 + t;
    int ox = gid & 127, oy = (gid >> 7) & 127, n = gid >> 14;
    float acc[32];
#pragma unroll
    for (int o = 0; o < 32; o++) acc[o] = 0.f;
    const float* xin = x + n * 65536;
#pragma unroll
    for (int ky = 0; ky < 4; ky++) {
        int iy = 2 * oy - 1 + ky;
        if (iy < 0 || iy >= 256) continue;
#pragma unroll
        for (int kx = 0; kx < 4; kx++) {
            int ix = 2 * ox - 1 + kx;
            if (ix < 0 || ix >= 256) continue;
            float v = xin[iy * 256 + ix];
#pragma unroll
            for (int o = 0; o < 32; o++) acc[o] = fmaf(v, sw[ky * 4 + kx][o], acc[o]);
        }
    }
    float* op = g_h1 + n * 524288 + oy * 128 + ox;
#pragma unroll
    for (int o = 0; o < 32; o++) op[o * 16384] = fmaxf(__fadd_rn(acc[o], sb[o]), 0.f);
}

// e2: conv 32->64, k4 s2 p1. g_h1 -> g_h2(64,64,64,64)
// ky-STREAMED input staging: per ky phase only rows {2r+ky} are staged
// (32ci x 16 x 35 = 70KB) + 32KB weights -> 102KB smem -> 2 CTAs/SM.
// Chain order (ky->kx->ci asc, acc=0, bias after) byte-identical to R10.
#define E2_IN_FL (32 * 16 * 35)     // 17920 per-ky slice
#define E2_W_FL  (4 * 32 * 64)      // 8192
#define E2_SMEM_B ((E2_IN_FL + E2_W_FL) * 4)
__global__ __launch_bounds__(256, 2) void k_e2(const float* __restrict__ w,
                                               const float* __restrict__ b) {
    extern __shared__ float sm[];
    float* sIn = sm;              // [ci][r16][35]  (rows 2r+ky of the halo tile)
    float* sw  = sm + E2_IN_FL;   // [kx][ci][o64]
    int tid = threadIdx.x;
    int og8 = tid >> 5;
    int sp = tid & 31;
    int r = sp >> 1, h = sp & 1;
    int t_y = blockIdx.x >> 2, t_x = blockIdx.x & 3;
    int n = blockIdx.y;
    int iy0 = 32 * t_y - 1, ix0 = 32 * t_x - 1;
    float acc[64];
#pragma unroll
    for (int i = 0; i < 64; i++) acc[i] = 0.f;
#pragma unroll
    for (int ky = 0; ky < 4; ky++) {
        __syncthreads();
        // stage input rows gy = iy0 + 2*rq + ky, rq = 0..15
        for (int idx = tid; idx < 32 * 16 * 34; idx += 256) {
            int ci = idx / 544, rr = idx - ci * 544;
            int rq = rr / 34, ix = rr - rq * 34;
            int gy = iy0 + 2 * rq + ky, gx = ix0 + ix;
            float v = 0.f;
            if (gy >= 0 && gy < 128 && gx >= 0 && gx < 128)
                v = g_h1[((n * 32 + ci) * 128 + gy) * 128 + gx];
            sIn[ci * 560 + rq * 35 + ix] = v;
        }
        for (int idx = tid; idx < E2_W_FL; idx += 256) {
            int kx = idx >> 11, ci = (idx >> 6) & 31, o = idx & 63;
            sw[idx] = w[(o * 32 + ci) * 16 + ky * 4 + kx];
        }
        __syncthreads();
#pragma unroll
        for (int kx = 0; kx < 4; kx++) {
            for (int ci = 0; ci < 32; ci++) {
                const float* vb = &sIn[ci * 560 + r * 35 + 16 * h + kx];
                float v[8];
#pragma unroll
                for (int j = 0; j < 8; j++) v[j] = vb[2 * j];
                const float4* wp = (const float4*)&sw[(kx * 32 + ci) * 64 + og8 * 8];
                float4 w0 = wp[0], w1 = wp[1];
                float wv[8] = {w0.x, w0.y, w0.z, w0.w, w1.x, w1.y, w1.z, w1.w};
#pragma unroll
                for (int j = 0; j < 8; j++)
#pragma unroll
                    for (int oo = 0; oo < 8; oo++)
                        acc[j * 8 + oo] = fmaf(v[j], wv[oo], acc[j * 8 + oo]);
            }
        }
    }
    int oy = 16 * t_y + r, ox0 = 16 * t_x + 8 * h;
#pragma unroll
    for (int oo = 0; oo < 8; oo++) {
        int o = og8 * 8 + oo;
        float bb = b[o];
        float* op = g_h2 + ((n * 64 + o) * 64 + oy) * 64 + ox0;
#pragma unroll
        for (int j = 0; j < 8; j++)
            op[j] = fmaxf(__fadd_rn(acc[j * 8 + oo], bb), 0.f);
    }
}

// e3: conv 64->64, k3 s1 p1. g_h2 -> ze (d_out)   (R10 proven)
#define E3_PITCH 21
#define E3_IN_FLOATS (64 * 18 * E3_PITCH)
#define E3_W_FLOATS  (3 * 64 * 64)
#define E3_SMEM_B   ((E3_IN_FLOATS + E3_W_FLOATS) * 4)
__global__ __launch_bounds__(256, 1) void k_e3(const float* __restrict__ w,
                                               const float* __restrict__ b,
                                               float* __restrict__ ze) {
    extern __shared__ float sm[];
    float* sIn = sm;                 // [ci][18][21]
    float* sw  = sm + E3_IN_FLOATS;  // [kx][ci][o]
    int tid = threadIdx.x;
    int og8 = tid >> 5;
    int sp = tid & 31;
    int r = sp >> 1, h = sp & 1;
    int t_y = blockIdx.x >> 2, t_x = blockIdx.x & 3;
    int n = blockIdx.y;
    int iy0 = 16 * t_y - 1, ix0 = 16 * t_x - 1;
    for (int idx = tid; idx < 64 * 18 * 18; idx += 256) {
        int ci = idx / 324, rr = idx - ci * 324;
        int iy = rr / 18, ix = rr - iy * 18;
        int gy = iy0 + iy, gx = ix0 + ix;
        float v = 0.f;
        if (gy >= 0 && gy < 64 && gx >= 0 && gx < 64)
            v = g_h2[((n * 64 + ci) * 64 + gy) * 64 + gx];
        sIn[ci * (18 * E3_PITCH) + iy * E3_PITCH + ix] = v;
    }
    float acc[64];
#pragma unroll
    for (int i = 0; i < 64; i++) acc[i] = 0.f;
#pragma unroll
    for (int ky = 0; ky < 3; ky++) {
        __syncthreads();
        for (int idx = tid; idx < E3_W_FLOATS; idx += 256) {
            int kx = idx >> 12, ci = (idx >> 6) & 63, o = idx & 63;
            sw[idx] = w[(o * 64 + ci) * 9 + ky * 3 + kx];
        }
        __syncthreads();
#pragma unroll
        for (int kx = 0; kx < 3; kx++) {
            for (int ci = 0; ci < 64; ci++) {
                const float* vb = &sIn[ci * (18 * E3_PITCH) + (r + ky) * E3_PITCH + 8 * h + kx];
                float v[8];
#pragma unroll
                for (int j = 0; j < 8; j++) v[j] = vb[j];
                const float4* wp = (const float4*)&sw[(kx * 64 + ci) * 64 + og8 * 8];
                float4 w0 = wp[0], w1 = wp[1];
                float wv[8] = {w0.x, w0.y, w0.z, w0.w, w1.x, w1.y, w1.z, w1.w};
#pragma unroll
                for (int j = 0; j < 8; j++)
#pragma unroll
                    for (int oo = 0; oo < 8; oo++)
                        acc[j * 8 + oo] = fmaf(v[j], wv[oo], acc[j * 8 + oo]);
            }
        }
    }
    int oy = 16 * t_y + r, ox0 = 16 * t_x + 8 * h;
#pragma unroll
    for (int oo = 0; oo < 8; oo++) {
        int o = og8 * 8 + oo;
        float bb = b[o];
        float* op = ze + ((n * 64 + o) * 64 + oy) * 64 + ox0;
#pragma unroll
        for (int j = 0; j < 8; j++)
            op[j] = fmaxf(__fadd_rn(acc[j * 8 + oo], bb), 0.f);
    }
}

// ===========================================================================
// VQ — GEMM-tiled, FROZEN chains; f32x2 code pairs (R16 proven, 437us)
// ===========================================================================
#define VQ_ZP 132
#define VQ_Z_FL   (64 * VQ_ZP)
#define VQ_E_FL   (64 * VQ_ZP)
#define VQ_SMEM_FL (VQ_Z_FL + VQ_E_FL + 128 + 128 + 128)
#define VQ_SMEM_B (VQ_SMEM_FL * 4)
__global__ __launch_bounds__(256, 2) void k_vq(const float* __restrict__ ze,
                                               const float* __restrict__ emb,
                                               float* __restrict__ zq) {
    extern __shared__ float sm[];
    float* sz   = sm;
    float* se   = sm + VQ_Z_FL;
    float* ssqz = sm + VQ_Z_FL + VQ_E_FL;
    float* snc  = ssqz + 128;
    int*   sbi  = (int*)(snc + 128);
    int tid = threadIdx.x;
    int pt = tid >> 4;
    int kt = tid & 15;

    int base = blockIdx.x * 128;
    int n = base >> 12;
    int rem = base & 4095;
    const float* zg = ze + n * 262144 + rem;

    for (int idx = tid; idx < 8192; idx += 256) {
        int c = idx >> 7, pos = idx & 127;
        sz[c * VQ_ZP + pos] = zg[c * 4096 + pos];
    }
    __syncthreads();
    if (tid < 128) {
        float s = 0.f;
#pragma unroll
        for (int c = 0; c < 64; c++) {
            float z = sz[c * VQ_ZP + tid];
            s = __fadd_rn(s, __fmul_rn(z, z));
        }
        ssqz[tid] = s;
    }

    float best[8];
    int bi[8];
#pragma unroll
    for (int p = 0; p < 8; p++) { best[p] = 3.4028235e38f; bi[p] = 0; }

    for (int ch = 0; ch < 4; ch++) {
        int kc0 = ch * 128;
        __syncthreads();
        for (int idx = tid; idx < 8192; idx += 256) {
            int k = idx >> 6, c = idx & 63;
            se[c * VQ_ZP + k] = emb[(kc0 + k) * 64 + c];
        }
        __syncthreads();
        if (tid < 128) {
            float s = 0.f;
#pragma unroll
            for (int c = 0; c < 64; c++) {
                float e = se[c * VQ_ZP + tid];
                s = __fadd_rn(s, __fmul_rn(e, e));
            }
            snc[tid] = s;
        }
        u64 acc2[32];                  // [p8][j2:4], lanes = codes (2*j2, 2*j2+1)
#pragma unroll
        for (int i = 0; i < 32; i++) acc2[i] = 0ull;
        const float* zp = sz + pt * 8;
        const float* ep = se + kt * 8;
        for (int c = 0; c < 64; c++) {
            float4 z0 = *(const float4*)(zp + c * VQ_ZP);
            float4 z1 = *(const float4*)(zp + c * VQ_ZP + 4);
            u64 z2[8];
            z2[0] = pack2(z0.x); z2[1] = pack2(z0.y);
            z2[2] = pack2(z0.z); z2[3] = pack2(z0.w);
            z2[4] = pack2(z1.x); z2[5] = pack2(z1.y);
            z2[6] = pack2(z1.z); z2[7] = pack2(z1.w);
            const ulonglong2* epp = (const ulonglong2*)(ep + c * VQ_ZP);
            ulonglong2 E0 = epp[0], E1 = epp[1];
            u64 e2v[4] = {E0.x, E0.y, E1.x, E1.y};
#pragma unroll
            for (int p = 0; p < 8; p++)
#pragma unroll
                for (int j2 = 0; j2 < 4; j2++)
                    fma2(acc2[p * 4 + j2], z2[p], e2v[j2]);
        }
        __syncthreads();
#pragma unroll
        for (int p = 0; p < 8; p++) {
            float sq = ssqz[pt * 8 + p];
#pragma unroll
            for (int j2 = 0; j2 < 4; j2++) {
                float2 d = unpack2(acc2[p * 4 + j2]);
                int k0i = kc0 + kt * 8 + 2 * j2;
                float q0 = __fadd_rn(__fsub_rn(sq, __fmul_rn(2.f, d.x)), snc[kt * 8 + 2 * j2]);
                if (q0 < best[p]) { best[p] = q0; bi[p] = k0i; }
                float q1 = __fadd_rn(__fsub_rn(sq, __fmul_rn(2.f, d.y)), snc[kt * 8 + 2 * j2 + 1]);
                if (q1 < best[p]) { best[p] = q1; bi[p] = k0i + 1; }
            }
        }
    }
#pragma unroll
    for (int p = 0; p < 8; p++) {
        float bv = best[p];
        int ii = bi[p];
#pragma unroll
        for (int off = 1; off < 16; off <<= 1) {
            float ov = __shfl_xor_sync(0xffffffffu, bv, off);
            int oi = __shfl_xor_sync(0xffffffffu, ii, off);
            if (ov < bv || (ov == bv && oi < ii)) { bv = ov; ii = oi; }
        }
        if (kt == 0) sbi[pt * 8 + p] = ii;
    }
    __syncthreads();
    {
        int pos = tid & 127;
        int c0 = (tid >> 7) * 32;
        int code = sbi[pos];
        const float* eg = emb + code * 64;
        float* zqp = zq + n * 262144 + rem + pos;
#pragma unroll
        for (int c = 0; c < 32; c++) {
            int cc = c0 + c;
            zqp[cc * 4096] = __ldg(eg + cc);
        }
    }
}

// ===========================================================================
// DECODER (1e-3 tolerance — R16 proven kernels)
// ===========================================================================

// d1: conv_t 64->32, k3 s1 p1; reads zq directly.
#define D1_CI 16
#define D1_IN_FL (D1_CI * 34 * 19)
#define D1_W_FL  (D1_CI * 9 * 32)
#define D1_SMEM_B ((D1_IN_FL + D1_W_FL) * 4)
__global__ __launch_bounds__(256, 2) void k_d1(const float* __restrict__ dec,
                                               const float* __restrict__ w,
                                               const float* __restrict__ b) {
    extern __shared__ float sm[];
    float* sIn = sm;
    float* sw  = sm + D1_IN_FL;
    int tid = threadIdx.x;
    int kt = tid & 3;
    int pt = tid >> 2;
    int r = pt >> 1, h = pt & 1;
    int ty = blockIdx.x >> 2, tx = blockIdx.x & 3;
    int n = blockIdx.y;
    int iy0 = 32 * ty - 1, ix0 = 16 * tx - 1;
    float acc[64];
#pragma unroll
    for (int i = 0; i < 64; i++) acc[i] = 0.f;
    for (int cc = 0; cc < 4; cc++) {
        int ci0 = cc * D1_CI;
        __syncthreads();
        for (int idx = tid; idx < D1_CI * 34 * 18; idx += 256) {
            int ci = idx / 612, rr = idx - ci * 612;
            int iy = rr / 18, ix = rr - iy * 18;
            int gy = iy0 + iy, gx = ix0 + ix;
            float v = 0.f;
            if (gy >= 0 && gy < 64 && gx >= 0 && gx < 64)
                v = dec[((n * 64 + ci0 + ci) * 64 + gy) * 64 + gx];
            sIn[ci * 646 + iy * 19 + ix] = v;
        }
        for (int idx = tid; idx < D1_W_FL; idx += 256) {
            int ci = idx / 288, rr = idx - ci * 288;
            int tap = rr >> 5, o = rr & 31;
            sw[(ci * 9 + tap) * 32 + o] = w[((ci0 + ci) * 32 + o) * 9 + (8 - tap)];
        }
        __syncthreads();
#pragma unroll 4
        for (int ci = 0; ci < D1_CI; ci++) {
#pragma unroll
            for (int ky = 0; ky < 3; ky++) {
                const float* vp = &sIn[ci * 646 + (r + ky) * 19 + 8 * h];
                float v[10];
#pragma unroll
                for (int i = 0; i < 10; i++) v[i] = vp[i];
#pragma unroll
                for (int kx = 0; kx < 3; kx++) {
                    const float4* wp = (const float4*)&sw[(ci * 9 + ky * 3 + kx) * 32 + kt * 8];
                    float4 w0 = wp[0], w1 = wp[1];
                    float wv[8] = {w0.x, w0.y, w0.z, w0.w, w1.x, w1.y, w1.z, w1.w};
#pragma unroll
                    for (int j = 0; j < 8; j++) {
                        float vv = v[kx + j];
#pragma unroll
                        for (int oo = 0; oo < 8; oo++)
                            acc[j * 8 + oo] = fmaf(vv, wv[oo], acc[j * 8 + oo]);
                    }
                }
            }
        }
    }
    int oy = 32 * ty + r, ox0 = 16 * tx + 8 * h;
#pragma unroll
    for (int oo = 0; oo < 8; oo++) {
        int o = kt * 8 + oo;
        float bb = b[o];
        float* op = g_d1 + ((n * 32 + o) * 64 + oy) * 64 + ox0;
#pragma unroll
        for (int j = 0; j < 8; j++)
            op[j] = fmaxf(acc[j * 8 + oo] + bb, 0.f);
    }
}

// d2: conv_t 32->64, k4 s2 p1. Parity-plane GEMM (R10 proven).
#define D2_IN_FL (32 * 17 * 18)
#define D2_W_FL  (4 * 32 * 64)
#define D2_SMEM_B ((D2_IN_FL + D2_W_FL) * 4)
__global__ __launch_bounds__(256, 2) void k_d2(const float* __restrict__ w,
                                               const float* __restrict__ b) {
    extern __shared__ float sm[];
    float* sIn = sm;
    float* sw  = sm + D2_IN_FL;
    int tid = threadIdx.x;
    int kt = tid & 7;
    int pt = tid >> 3;
    int Yr = pt >> 1, h = pt & 1;
    int bx = blockIdx.x;
    int pe = bx >> 4;
    int e = pe >> 1, f = pe & 1;
    int tile = bx & 15;
    int tY = tile >> 2, tX = tile & 3;
    int n = blockIdx.y;
    int py = 1 - e, px = 1 - f;
    int iy0 = 16 * tY + e - 1, ix0 = 16 * tX + f - 1;
    for (int idx = tid; idx < 32 * 17 * 17; idx += 256) {
        int ci = idx / 289, rr = idx - ci * 289;
        int iy = rr / 17, ix = rr - iy * 17;
        int gy = iy0 + iy, gx = ix0 + ix;
        float v = 0.f;
        if (gy >= 0 && gy < 64 && gx >= 0 && gx < 64)
            v = g_d1[((n * 32 + ci) * 64 + gy) * 64 + gx];
        sIn[ci * 306 + iy * 18 + ix] = v;
    }
    for (int idx = tid; idx < D2_W_FL; idx += 256) {
        int t4 = idx >> 11, ci = (idx >> 6) & 31, o = idx & 63;
        int tky = t4 >> 1, tkx = t4 & 1;
        sw[idx] = w[(ci * 64 + o) * 16 + (py + 2 * tky) * 4 + (px + 2 * tkx)];
    }
    __syncthreads();
    float acc[64];
#pragma unroll
    for (int i = 0; i < 64; i++) acc[i] = 0.f;
#pragma unroll 4
    for (int ci = 0; ci < 32; ci++) {
        const float* pa = &sIn[ci * 306 + (Yr + 1) * 18 + 8 * h];
        const float* pb = pa - 18;
        float va[9], vb[9];
#pragma unroll
        for (int i = 0; i < 9; i++) { va[i] = pa[i]; vb[i] = pb[i]; }
#pragma unroll
        for (int tky = 0; tky < 2; tky++) {
#pragma unroll
            for (int tkx = 0; tkx < 2; tkx++) {
                int t4 = tky * 2 + tkx;
                const float4* wp = (const float4*)&sw[(t4 * 32 + ci) * 64 + kt * 8];
                float4 w0 = wp[0], w1 = wp[1];
                float wv[8] = {w0.x, w0.y, w0.z, w0.w, w1.x, w1.y, w1.z, w1.w};
#pragma unroll
                for (int j = 0; j < 8; j++) {
                    float v = tky ? vb[j + 1 - tkx] : va[j + 1 - tkx];
#pragma unroll
                    for (int oo = 0; oo < 8; oo++)
                        acc[j * 8 + oo] = fmaf(v, wv[oo], acc[j * 8 + oo]);
                }
            }
        }
    }
    int y = 32 * tY + 2 * Yr + e;
    int xbase = 32 * tX + 16 * h + f;
#pragma unroll
    for (int oo = 0; oo < 8; oo++) {
        int o = kt * 8 + oo;
        float bb = b[o];
        float* op = g_d2 + ((n * 64 + o) * 128 + y) * 128 + xbase;
#pragma unroll
        for (int j = 0; j < 8; j++)
            op[2 * j] = fmaxf(acc[j * 8 + oo] + bb, 0.f);
    }
}

// d3: conv_t 64->1, k4 s2 p1 -> x_hat (R16 version)
#define D3_IN_FL (64 * 18 * 19)    // 21888
#define D3_W_FL  (4 * 64 * 4)      // 1024
#define D3_SMEM_B ((D3_IN_FL + D3_W_FL) * 4)
__global__ __launch_bounds__(256, 2) void k_d3(const float* __restrict__ w,
                                               const float* __restrict__ b,
                                               float* __restrict__ xh) {
    extern __shared__ float sm[];
    float* sIn = sm;               // [ci][18][19]
    float* swp = sm + D3_IN_FL;    // [p][ci][4]
    int tid = threadIdx.x;
    int p = tid >> 6;
    int sub = tid & 63;
    int rr = sub >> 2;
    int xq = sub & 3;
    int e = p >> 1, f = p & 1;
    int ty = blockIdx.x >> 3, tx = blockIdx.x & 7;
    int n = blockIdx.y;
    int iy0 = 16 * ty - 1, ix0 = 16 * tx - 1;
    for (int idx = tid; idx < 64 * 18 * 18; idx += 256) {
        int ci = idx / 324, r2 = idx - ci * 324;
        int iy = r2 / 18, ix = r2 - iy * 18;
        int gy = iy0 + iy, gx = ix0 + ix;
        float v = 0.f;
        if (gy >= 0 && gy < 128 && gx >= 0 && gx < 128)
            v = g_d2[((n * 64 + ci) * 128 + gy) * 128 + gx];
        sIn[ci * 342 + iy * 19 + ix] = v;
    }
    for (int idx = tid; idx < D3_W_FL; idx += 256) {
        int pp = idx >> 8;
        int ci = (idx >> 2) & 63;
        int t4 = idx & 3;
        int tyt = t4 >> 1, txt = t4 & 1;
        int pye = 1 - (pp >> 1), pxe = 1 - (pp & 1);
        swp[idx] = w[ci * 16 + (pye + 2 * tyt) * 4 + (pxe + 2 * txt)];
    }
    __syncthreads();
    float acc[4];
#pragma unroll
    for (int d = 0; d < 4; d++) acc[d] = 0.f;
    int rowA = rr + e + 1;
    int c0 = 4 * xq + f;
#pragma unroll 8
    for (int ci = 0; ci < 64; ci++) {
        const float* pa = &sIn[ci * 342 + rowA * 19 + c0];
        const float* pb = pa - 19;
        float va[5], vb[5];
#pragma unroll
        for (int i = 0; i < 5; i++) { va[i] = pa[i]; vb[i] = pb[i]; }
        float4 w4 = *(const float4*)&swp[(p * 64 + ci) * 4];
#pragma unroll
        for (int d = 0; d < 4; d++) {
            acc[d] = fmaf(va[d + 1], w4.x, acc[d]);
            acc[d] = fmaf(va[d],     w4.y, acc[d]);
            acc[d] = fmaf(vb[d + 1], w4.z, acc[d]);
            acc[d] = fmaf(vb[d],     w4.w, acc[d]);
        }
    }
    float bb = b[0];
    int y = 32 * ty + 2 * rr + e;
    float* op = xh + n * 65536 + y * 256 + 32 * tx + 8 * xq + f;
#pragma unroll
    for (int d = 0; d < 4; d++)
        op[2 * d] = acc[d] + bb;
}

// ---------------------------------------------------------------------------
extern "C" void kernel_launch(void* const* d_in, const int* in_sizes, int n_in,
                              void* d_out, int out_size) {
    const float* x   = (const float*)d_in[0];
    const float* e1w = (const float*)d_in[1];
    const float* e1b = (const float*)d_in[2];
    const float* e2w = (const float*)d_in[3];
    const float* e2b = (const float*)d_in[4];
    const float* e3w = (const float*)d_in[5];
    const float* e3b = (const float*)d_in[6];
    const float* emb = (const float*)d_in[7];
    const float* d1w = (const float*)d_in[8];
    const float* d1b = (const float*)d_in[9];
    const float* d2w = (const float*)d_in[10];
    const float* d2b = (const float*)d_in[11];
    const float* d3w = (const float*)d_in[12];
    const float* d3b = (const float*)d_in[13];
    float* out = (float*)d_out;
    float* ze = out + OFF_ZE;
    float* zq = out + OFF_ZQ;

    cudaFuncSetAttribute(k_e2, cudaFuncAttributeMaxDynamicSharedMemorySize, E2_SMEM_B);
    cudaFuncSetAttribute(k_e3, cudaFuncAttributeMaxDynamicSharedMemorySize, E3_SMEM_B);
    cudaFuncSetAttribute(k_vq, cudaFuncAttributeMaxDynamicSharedMemorySize, VQ_SMEM_B);
    cudaFuncSetAttribute(k_d1, cudaFuncAttributeMaxDynamicSharedMemorySize, D1_SMEM_B);
    cudaFuncSetAttribute(k_d2, cudaFuncAttributeMaxDynamicSharedMemorySize, D2_SMEM_B);
    cudaFuncSetAttribute(k_d3, cudaFuncAttributeMaxDynamicSharedMemorySize, D3_SMEM_B);

    k_e1<<<4096, 256>>>(x, e1w, e1b);
    k_e2<<<dim3(16, 64), 256, E2_SMEM_B>>>(e2w, e2b);
    k_e3<<<dim3(16, 64), 256, E3_SMEM_B>>>(e3w, e3b, ze);
    k_vq<<<2048, 256, VQ_SMEM_B>>>(ze, emb, zq);
    k_d1<<<dim3(8, 64), 256, D1_SMEM_B>>>(zq, d1w, d1b);
    k_d2<<<dim3(64, 64), 256, D2_SMEM_B>>>(d2w, d2b);
    k_d3<<<dim3(64, 64), 256, D3_SMEM_B>>>(d3w, d3b, out);
}